// round 1
// baseline (speedup 1.0000x reference)
#include <cuda_runtime.h>
#include <cstdint>

#define DIM 1536
#define NH 12
#define HD 128
#define S_MAX 4680

// ---------------- scratch (device globals: no allocation allowed) ----------------
__device__ float g_qraw[S_MAX * DIM];
__device__ float g_kraw[S_MAX * DIM];
__device__ float g_vbuf[S_MAX * DIM];
__device__ float g_rq[S_MAX * DIM];
__device__ float g_rk[S_MAX * DIM];
__device__ float g_att[S_MAX * DIM];
__device__ float g_rope[S_MAX * HD];     // [s][64 pairs][2] (cos,sin)
__device__ float g_z[S_MAX * NH];
__device__ float g_M[NH * HD * HD];      // M[n][d][j] = sum_m g_kv[n,d,m]*Wlin[j,m]

// ---------------- rope table ----------------
// rope[s][i] = freqs[row][i], row = f if i<22, h if i<43, else w
__global__ void rope_table_k(const float* __restrict__ freqs,
                             const int* __restrict__ hg, const int* __restrict__ wg) {
    int s = blockIdx.x;
    int i = threadIdx.x;             // 0..63
    int h = hg[0], w = wg[0];
    int hw = h * w;
    int fi = s / hw;
    int rem = s - fi * hw;
    int hi = rem / w;
    int wi = rem - hi * w;
    int r = (i < 22) ? fi : ((i < 43) ? hi : wi);
    float2 v = ((const float2*)freqs)[r * 64 + i];
    ((float2*)g_rope)[s * 64 + i] = v;
}

// ---------------- generic NT GEMM: C[M,1536] = A[M,1536] * B[1536,1536]^T + bias ----------------
__global__ __launch_bounds__(256) void gemm_nt(const float* __restrict__ A,
                                               const float* __restrict__ B,
                                               const float* __restrict__ bias,
                                               float* __restrict__ C, int M) {
    __shared__ float As[16][129];
    __shared__ float Bs[16][129];
    const int tid = threadIdx.x;
    const int ty = tid >> 4, tx = tid & 15;
    const int mbase = blockIdx.x * 128;
    const int nbase = blockIdx.y * 128;
    const int lr = tid >> 1;
    const int lk = (tid & 1) * 8;
    const float* Ap = A + (size_t)(mbase + lr) * DIM + lk;
    const float* Bp = B + (size_t)(nbase + lr) * DIM + lk;
    const bool aval = (mbase + lr) < M;

    float acc[8][8];
#pragma unroll
    for (int i = 0; i < 8; i++)
#pragma unroll
        for (int j = 0; j < 8; j++) acc[i][j] = 0.f;

    for (int kt = 0; kt < DIM; kt += 16) {
        float4 a0 = make_float4(0, 0, 0, 0), a1 = a0;
        if (aval) { a0 = *(const float4*)Ap; a1 = *(const float4*)(Ap + 4); }
        float4 b0 = *(const float4*)Bp;
        float4 b1 = *(const float4*)(Bp + 4);
        __syncthreads();
        As[lk + 0][lr] = a0.x; As[lk + 1][lr] = a0.y; As[lk + 2][lr] = a0.z; As[lk + 3][lr] = a0.w;
        As[lk + 4][lr] = a1.x; As[lk + 5][lr] = a1.y; As[lk + 6][lr] = a1.z; As[lk + 7][lr] = a1.w;
        Bs[lk + 0][lr] = b0.x; Bs[lk + 1][lr] = b0.y; Bs[lk + 2][lr] = b0.z; Bs[lk + 3][lr] = b0.w;
        Bs[lk + 4][lr] = b1.x; Bs[lk + 5][lr] = b1.y; Bs[lk + 6][lr] = b1.z; Bs[lk + 7][lr] = b1.w;
        __syncthreads();
#pragma unroll
        for (int k = 0; k < 16; k++) {
            float a[8], b[8];
#pragma unroll
            for (int i = 0; i < 8; i++) a[i] = As[k][ty * 8 + i];
#pragma unroll
            for (int j = 0; j < 8; j++) b[j] = Bs[k][tx + 16 * j];
#pragma unroll
            for (int i = 0; i < 8; i++)
#pragma unroll
                for (int j = 0; j < 8; j++) acc[i][j] += a[i] * b[j];
        }
        Ap += 16;
        Bp += 16;
    }
#pragma unroll
    for (int i = 0; i < 8; i++) {
        int r = mbase + ty * 8 + i;
        if (r < M) {
#pragma unroll
            for (int j = 0; j < 8; j++) {
                int c = nbase + tx + 16 * j;
                C[(size_t)r * DIM + c] = acc[i][j] + bias[c];
            }
        }
    }
}

// ---------------- RMS norm (over full 1536) + RoPE + optional z ----------------
// 384 threads: warp w == head w, thread handles 4 consecutive elements (one float4).
__global__ __launch_bounds__(384) void rmsrope_k(const float* __restrict__ in,
                                                 const float* __restrict__ g,
                                                 const float* __restrict__ gkm,
                                                 float* __restrict__ out,
                                                 float* __restrict__ zout, int doZ) {
    const int s = blockIdx.x;
    const int t = threadIdx.x;
    const int warp = t >> 5, lane = t & 31;
    float4 v = ((const float4*)(in + (size_t)s * DIM))[t];
    float ss = v.x * v.x + v.y * v.y + v.z * v.z + v.w * v.w;
#pragma unroll
    for (int off = 16; off; off >>= 1) ss += __shfl_xor_sync(~0u, ss, off);
    __shared__ float red[12];
    __shared__ float sinv;
    if (lane == 0) red[warp] = ss;
    __syncthreads();
    if (t == 0) {
        float tot = 0;
#pragma unroll
        for (int i = 0; i < 12; i++) tot += red[i];
        sinv = rsqrtf(tot * (1.0f / DIM) + 1e-6f);
    }
    __syncthreads();
    const float inv = sinv;
    const int e = t * 4;
    float y0 = v.x * inv * g[e + 0];
    float y1 = v.y * inv * g[e + 1];
    float y2 = v.z * inv * g[e + 2];
    float y3 = v.w * inv * g[e + 3];
    if (doZ) {
        float zp = fmaxf(y0, 0.f) * gkm[e + 0] + fmaxf(y1, 0.f) * gkm[e + 1] +
                   fmaxf(y2, 0.f) * gkm[e + 2] + fmaxf(y3, 0.f) * gkm[e + 3];
#pragma unroll
        for (int off = 16; off; off >>= 1) zp += __shfl_xor_sync(~0u, zp, off);
        if (lane == 0) zout[s * NH + warp] = 1.0f / (zp + 1e-6f);
    }
    // pair index within head: i0 = (2t) mod 64; pairs (y0,y1),(y2,y3)
    const int i0 = (2 * t) & 63;
    const float* rp = g_rope + (size_t)s * HD + i0 * 2;
    float c0 = rp[0], s0 = rp[1], c1 = rp[2], s1 = rp[3];
    float o0 = y0 * c0 - y1 * s0;
    float o1 = y0 * s0 + y1 * c0;
    float o2 = y2 * c1 - y3 * s1;
    float o3 = y2 * s1 + y3 * c1;
    ((float4*)(out + (size_t)s * DIM))[t] = make_float4(o0, o1, o2, o3);
}

// ---------------- flash attention (fp32 SIMT, 64x64 tiles) ----------------
#define ATT_SMEM_FLOATS (64 * 129 * 2 + 64 * 65)
#define ATT_SMEM_BYTES (ATT_SMEM_FLOATS * 4)

__global__ __launch_bounds__(256, 2) void attn_k(const float* __restrict__ RQ,
                                                 const float* __restrict__ RK,
                                                 const float* __restrict__ V,
                                                 float* __restrict__ O, int S) {
    extern __shared__ float sm[];
    float* Qs  = sm;                 // [64][129]
    float* KVs = sm + 64 * 129;      // [64][129]
    float* Ps  = sm + 2 * 64 * 129;  // [64][65]
    const int tid = threadIdx.x;
    const int ty = tid >> 4, tx = tid & 15;
    const int n = blockIdx.y;
    const int qbase = blockIdx.x * 64;
    const int lrow = tid >> 2, lc = tid & 3;

    // load Q tile
    {
        const float* src = RQ + (size_t)(qbase + lrow) * DIM + n * HD + lc * 4;
        const bool valid = (qbase + lrow) < S;
        float* dst0 = Qs + lrow * 129 + lc * 4;
#pragma unroll
        for (int i = 0; i < 8; i++) {
            float4 q = valid ? *(const float4*)(src + i * 16) : make_float4(0, 0, 0, 0);
            float* dst = dst0 + i * 16;
            dst[0] = q.x; dst[1] = q.y; dst[2] = q.z; dst[3] = q.w;
        }
    }

    float o[4][8];
    float m[4], l[4];
#pragma unroll
    for (int i = 0; i < 4; i++) {
        m[i] = -1e30f;
        l[i] = 0.f;
#pragma unroll
        for (int j = 0; j < 8; j++) o[i][j] = 0.f;
    }
    const int nkt = (S + 63) >> 6;
    const float scale = 0.08838834764831845f;  // 128^-0.5

    for (int kt = 0; kt < nkt; kt++) {
        const int kb = kt * 64;
        __syncthreads();  // prev PV done reading KVs/Ps
        // load K tile
        {
            const float* src = RK + (size_t)(kb + lrow) * DIM + n * HD + lc * 4;
            const bool valid = (kb + lrow) < S;
            float* dst0 = KVs + lrow * 129 + lc * 4;
#pragma unroll
            for (int i = 0; i < 8; i++) {
                float4 k = valid ? *(const float4*)(src + i * 16) : make_float4(0, 0, 0, 0);
                float* dst = dst0 + i * 16;
                dst[0] = k.x; dst[1] = k.y; dst[2] = k.z; dst[3] = k.w;
            }
        }
        __syncthreads();
        // scores: rows ty*4+i, cols tx+16*j
        float sc[4][4];
#pragma unroll
        for (int i = 0; i < 4; i++)
#pragma unroll
            for (int j = 0; j < 4; j++) sc[i][j] = 0.f;
#pragma unroll 4
        for (int k = 0; k < 128; k++) {
            float a[4], b[4];
#pragma unroll
            for (int i = 0; i < 4; i++) a[i] = Qs[(ty * 4 + i) * 129 + k];
#pragma unroll
            for (int j = 0; j < 4; j++) b[j] = KVs[(tx + 16 * j) * 129 + k];
#pragma unroll
            for (int i = 0; i < 4; i++)
#pragma unroll
                for (int j = 0; j < 4; j++) sc[i][j] += a[i] * b[j];
        }
        // online softmax
#pragma unroll
        for (int i = 0; i < 4; i++) {
            float tm = -1e30f;
#pragma unroll
            for (int j = 0; j < 4; j++) {
                float v2 = sc[i][j] * scale;
                if (kb + tx + 16 * j >= S) v2 = -1e30f;
                sc[i][j] = v2;
                tm = fmaxf(tm, v2);
            }
#pragma unroll
            for (int off = 8; off; off >>= 1) tm = fmaxf(tm, __shfl_xor_sync(~0u, tm, off));
            float mn = fmaxf(m[i], tm);
            float f = __expf(m[i] - mn);
            float rs = 0.f;
#pragma unroll
            for (int j = 0; j < 4; j++) {
                float p = __expf(sc[i][j] - mn);
                Ps[(ty * 4 + i) * 65 + tx + 16 * j] = p;
                rs += p;
            }
#pragma unroll
            for (int off = 8; off; off >>= 1) rs += __shfl_xor_sync(~0u, rs, off);
            l[i] = l[i] * f + rs;
            m[i] = mn;
#pragma unroll
            for (int j = 0; j < 8; j++) o[i][j] *= f;
        }
        __syncthreads();  // scores done reading KVs (K); Ps written
        // load V tile into KVs
        {
            const float* src = V + (size_t)(kb + lrow) * DIM + n * HD + lc * 4;
            const bool valid = (kb + lrow) < S;
            float* dst0 = KVs + lrow * 129 + lc * 4;
#pragma unroll
            for (int i = 0; i < 8; i++) {
                float4 v = valid ? *(const float4*)(src + i * 16) : make_float4(0, 0, 0, 0);
                float* dst = dst0 + i * 16;
                dst[0] = v.x; dst[1] = v.y; dst[2] = v.z; dst[3] = v.w;
            }
        }
        __syncthreads();
        // PV: O[r][tx+16*j] += sum_c P[r][c] * V[c][tx+16*j]
#pragma unroll 2
        for (int c = 0; c < 64; c++) {
            float p[4], vv[8];
#pragma unroll
            for (int i = 0; i < 4; i++) p[i] = Ps[(ty * 4 + i) * 65 + c];
#pragma unroll
            for (int j = 0; j < 8; j++) vv[j] = KVs[c * 129 + tx + 16 * j];
#pragma unroll
            for (int i = 0; i < 4; i++)
#pragma unroll
                for (int j = 0; j < 8; j++) o[i][j] += p[i] * vv[j];
        }
    }
    // epilogue
#pragma unroll
    for (int i = 0; i < 4; i++) {
        int r = qbase + ty * 4 + i;
        if (r < S) {
            float invl = 1.0f / l[i];
#pragma unroll
            for (int j = 0; j < 8; j++)
                O[(size_t)r * DIM + n * HD + tx + 16 * j] = o[i][j] * invl;
        }
    }
}

// ---------------- M[n][d][j] = sum_m g_kv[n,d,m] * Wlin[j,m] ----------------
__global__ __launch_bounds__(256) void prepM_k(const float* __restrict__ g_kv,
                                               const float* __restrict__ Wlin) {
    int o = blockIdx.x * 256 + threadIdx.x;  // 768*256 = 12*128*128
    int n = o >> 14;
    int d = (o >> 7) & 127;
    int j = o & 127;
    const float* gp = g_kv + ((size_t)n * 128 + d) * 128;
    const float* wp = Wlin + (size_t)j * 128;
    float acc = 0.f;
#pragma unroll 8
    for (int mm = 0; mm < 128; mm++) acc += gp[mm] * wp[mm];
    g_M[o] = acc;
}

// ---------------- gated branch: att += z * (rq @ M_n) + blin ----------------
__global__ __launch_bounds__(128) void gated_k(const float* __restrict__ RQ,
                                               const float* __restrict__ blin,
                                               float* __restrict__ att) {
    const int s = blockIdx.x, n = blockIdx.y, j = threadIdx.x;
    __shared__ float rs[128];
    rs[j] = RQ[(size_t)s * DIM + n * HD + j];
    __syncthreads();
    const float* Mp = g_M + (size_t)n * (HD * HD) + j;
    float acc = 0.f;
#pragma unroll 16
    for (int d = 0; d < 128; d++) acc += rs[d] * Mp[(size_t)d * 128];
    const size_t idx = (size_t)s * DIM + n * HD + j;
    att[idx] += acc * g_z[s * NH + n] + blin[j];
}

// ---------------- host ----------------
extern "C" void kernel_launch(void* const* d_in, const int* in_sizes, int n_in,
                              void* d_out, int out_size) {
    const float* x       = (const float*)d_in[0];
    const float* freqs   = (const float*)d_in[1];
    const float* g_kmean = (const float*)d_in[2];
    const float* g_kv    = (const float*)d_in[3];
    const float* Wq = (const float*)d_in[4];  const float* bq = (const float*)d_in[5];
    const float* Wk = (const float*)d_in[6];  const float* bk = (const float*)d_in[7];
    const float* Wv = (const float*)d_in[8];  const float* bv = (const float*)d_in[9];
    const float* Wo = (const float*)d_in[10]; const float* bo = (const float*)d_in[11];
    const float* gq = (const float*)d_in[12]; const float* gk = (const float*)d_in[13];
    const float* Wlin = (const float*)d_in[14]; const float* blin = (const float*)d_in[15];
    const int* hG = (const int*)d_in[17];
    const int* wG = (const int*)d_in[18];
    float* out = (float*)d_out;

    int S = in_sizes[0] / DIM;
    if (S > S_MAX) S = S_MAX;

    cudaFuncSetAttribute(attn_k, cudaFuncAttributeMaxDynamicSharedMemorySize, ATT_SMEM_BYTES);

    float *qraw, *kraw, *vbuf, *rq, *rk, *att, *z;
    cudaGetSymbolAddress((void**)&qraw, g_qraw);
    cudaGetSymbolAddress((void**)&kraw, g_kraw);
    cudaGetSymbolAddress((void**)&vbuf, g_vbuf);
    cudaGetSymbolAddress((void**)&rq, g_rq);
    cudaGetSymbolAddress((void**)&rk, g_rk);
    cudaGetSymbolAddress((void**)&att, g_att);
    cudaGetSymbolAddress((void**)&z, g_z);

    dim3 gemmGrid((S + 127) / 128, DIM / 128);

    rope_table_k<<<S, 64>>>(freqs, hG, wG);
    gemm_nt<<<gemmGrid, 256>>>(x, Wq, bq, qraw, S);
    gemm_nt<<<gemmGrid, 256>>>(x, Wk, bk, kraw, S);
    gemm_nt<<<gemmGrid, 256>>>(x, Wv, bv, vbuf, S);
    rmsrope_k<<<S, 384>>>(qraw, gq, g_kmean, rq, z, 1);
    rmsrope_k<<<S, 384>>>(kraw, gk, g_kmean, rk, z, 0);
    prepM_k<<<768, 256>>>(g_kv, Wlin);
    attn_k<<<dim3((S + 63) / 64, NH), 256, ATT_SMEM_BYTES>>>(rq, rk, vbuf, att, S);
    gated_k<<<dim3(S, NH), 128>>>(rq, blin, att);
    gemm_nt<<<gemmGrid, 256>>>(att, Wo, bo, out, S);
}

// round 2
// speedup vs baseline: 2.1449x; 2.1449x over previous
#include <cuda_runtime.h>
#include <cstdint>

#define DIM 1536
#define NH 12
#define HD 128
#define S_MAX 4680

// ---------------- scratch ----------------
__device__ float g_qraw[S_MAX * DIM];
__device__ float g_kraw[S_MAX * DIM];
__device__ float g_vbuf[S_MAX * DIM];
__device__ float g_rq[S_MAX * DIM];
__device__ float g_rk[S_MAX * DIM];
__device__ float g_att[S_MAX * DIM];
__device__ float g_rope[S_MAX * HD];
__device__ float g_z[S_MAX * NH];
__device__ float g_M[NH * HD * HD];

// ---------------- tf32 helpers ----------------
__device__ __forceinline__ uint32_t f2tf(float x) {
    uint32_t r; asm("cvt.rna.tf32.f32 %0, %1;" : "=r"(r) : "f"(x)); return r;
}
__device__ __forceinline__ void mma8(float* c, uint32_t a0, uint32_t a1, uint32_t a2, uint32_t a3,
                                     uint32_t b0, uint32_t b1) {
    asm volatile(
        "mma.sync.aligned.m16n8k8.row.col.f32.tf32.tf32.f32 "
        "{%0,%1,%2,%3},{%4,%5,%6,%7},{%8,%9},{%0,%1,%2,%3};\n"
        : "+f"(c[0]), "+f"(c[1]), "+f"(c[2]), "+f"(c[3])
        : "r"(a0), "r"(a1), "r"(a2), "r"(a3), "r"(b0), "r"(b1));
}
// XOR swizzle within 32-word (128B) segments: conflict-free mma fragment loads
__device__ __forceinline__ int sx(int r, int d) {
    return (d & ~31) | ((((d >> 2) ^ r) & 7) << 2) | (d & 3);
}

// ---------------- rope table ----------------
__global__ void rope_table_k(const float* __restrict__ freqs,
                             const int* __restrict__ hg, const int* __restrict__ wg) {
    int s = blockIdx.x;
    int i = threadIdx.x;
    int h = hg[0], w = wg[0];
    int hw = h * w;
    int fi = s / hw;
    int rem = s - fi * hw;
    int hi = rem / w;
    int wi = rem - hi * w;
    int r = (i < 22) ? fi : ((i < 43) ? hi : wi);
    float2 v = ((const float2*)freqs)[r * 64 + i];
    ((float2*)g_rope)[s * 64 + i] = v;
}

// ---------------- tf32 NT GEMM: C[M,1536] = A * B^T + bias ----------------
__global__ __launch_bounds__(256) void gemm_tf32(const float* __restrict__ A,
                                                 const float* __restrict__ B,
                                                 const float* __restrict__ bias,
                                                 float* __restrict__ C, int M) {
    __shared__ uint32_t As[128 * 32];
    __shared__ uint32_t Bs[128 * 32];
    const int tid = threadIdx.x;
    const int lane = tid & 31, warp = tid >> 5;
    const int wm = warp >> 2, wn = warp & 3;
    const int q = lane & 3, g2 = lane >> 2;
    const int mbase = blockIdx.x * 128, nbase = blockIdx.y * 128;

    float acc[4][4][4];
#pragma unroll
    for (int i = 0; i < 4; i++)
#pragma unroll
        for (int j = 0; j < 4; j++)
#pragma unroll
            for (int k = 0; k < 4; k++) acc[i][j][k] = 0.f;

    for (int kt = 0; kt < DIM; kt += 32) {
        __syncthreads();
#pragma unroll
        for (int it = 0; it < 4; it++) {
            int f = tid + it * 256;
            int kg = f & 7, m = f >> 3;
            float4 av = make_float4(0, 0, 0, 0);
            if (mbase + m < M) av = *(const float4*)(A + (size_t)(mbase + m) * DIM + kt + kg * 4);
            uint4 at;
            at.x = f2tf(av.x); at.y = f2tf(av.y); at.z = f2tf(av.z); at.w = f2tf(av.w);
            *(uint4*)(As + m * 32 + (((kg ^ m) & 7) << 2)) = at;
            float4 bv = *(const float4*)(B + (size_t)(nbase + m) * DIM + kt + kg * 4);
            uint4 bt;
            bt.x = f2tf(bv.x); bt.y = f2tf(bv.y); bt.z = f2tf(bv.z); bt.w = f2tf(bv.w);
            *(uint4*)(Bs + m * 32 + (((kg ^ m) & 7) << 2)) = bt;
        }
        __syncthreads();
#pragma unroll
        for (int ks = 0; ks < 4; ks++) {
            uint32_t af[4][4], bf[4][2];
#pragma unroll
            for (int mt = 0; mt < 4; mt++) {
                int r0 = wm * 64 + mt * 16 + g2;
                af[mt][0] = As[r0 * 32 + sx(r0, 8 * ks + q)];
                af[mt][1] = As[(r0 + 8) * 32 + sx(r0 + 8, 8 * ks + q)];
                af[mt][2] = As[r0 * 32 + sx(r0, 8 * ks + q + 4)];
                af[mt][3] = As[(r0 + 8) * 32 + sx(r0 + 8, 8 * ks + q + 4)];
            }
#pragma unroll
            for (int nt = 0; nt < 4; nt++) {
                int n0 = wn * 32 + nt * 8 + g2;
                bf[nt][0] = Bs[n0 * 32 + sx(n0, 8 * ks + q)];
                bf[nt][1] = Bs[n0 * 32 + sx(n0, 8 * ks + q + 4)];
            }
#pragma unroll
            for (int mt = 0; mt < 4; mt++)
#pragma unroll
                for (int nt = 0; nt < 4; nt++)
                    mma8(acc[mt][nt], af[mt][0], af[mt][1], af[mt][2], af[mt][3],
                         bf[nt][0], bf[nt][1]);
        }
    }
#pragma unroll
    for (int mt = 0; mt < 4; mt++) {
        int r0 = mbase + wm * 64 + mt * 16 + g2;
#pragma unroll
        for (int nt = 0; nt < 4; nt++) {
            int c0 = nbase + wn * 32 + nt * 8 + 2 * q;
            if (r0 < M) {
                C[(size_t)r0 * DIM + c0]     = acc[mt][nt][0] + bias[c0];
                C[(size_t)r0 * DIM + c0 + 1] = acc[mt][nt][1] + bias[c0 + 1];
            }
            if (r0 + 8 < M) {
                C[(size_t)(r0 + 8) * DIM + c0]     = acc[mt][nt][2] + bias[c0];
                C[(size_t)(r0 + 8) * DIM + c0 + 1] = acc[mt][nt][3] + bias[c0 + 1];
            }
        }
    }
}

// ---------------- RMS + RoPE + optional z ----------------
__global__ __launch_bounds__(384) void rmsrope_k(const float* __restrict__ in,
                                                 const float* __restrict__ g,
                                                 const float* __restrict__ gkm,
                                                 float* __restrict__ out,
                                                 float* __restrict__ zout, int doZ) {
    const int s = blockIdx.x;
    const int t = threadIdx.x;
    const int warp = t >> 5, lane = t & 31;
    float4 v = ((const float4*)(in + (size_t)s * DIM))[t];
    float ss = v.x * v.x + v.y * v.y + v.z * v.z + v.w * v.w;
#pragma unroll
    for (int off = 16; off; off >>= 1) ss += __shfl_xor_sync(~0u, ss, off);
    __shared__ float red[12];
    __shared__ float sinv;
    if (lane == 0) red[warp] = ss;
    __syncthreads();
    if (t == 0) {
        float tot = 0;
#pragma unroll
        for (int i = 0; i < 12; i++) tot += red[i];
        sinv = rsqrtf(tot * (1.0f / DIM) + 1e-6f);
    }
    __syncthreads();
    const float inv = sinv;
    const int e = t * 4;
    float y0 = v.x * inv * g[e + 0];
    float y1 = v.y * inv * g[e + 1];
    float y2 = v.z * inv * g[e + 2];
    float y3 = v.w * inv * g[e + 3];
    if (doZ) {
        float zp = fmaxf(y0, 0.f) * gkm[e + 0] + fmaxf(y1, 0.f) * gkm[e + 1] +
                   fmaxf(y2, 0.f) * gkm[e + 2] + fmaxf(y3, 0.f) * gkm[e + 3];
#pragma unroll
        for (int off = 16; off; off >>= 1) zp += __shfl_xor_sync(~0u, zp, off);
        if (lane == 0) zout[s * NH + warp] = 1.0f / (zp + 1e-6f);
    }
    const int i0 = (2 * t) & 63;
    const float* rp = g_rope + (size_t)s * HD + i0 * 2;
    float c0 = rp[0], s0 = rp[1], c1 = rp[2], s1 = rp[3];
    float o0 = y0 * c0 - y1 * s0;
    float o1 = y0 * s0 + y1 * c0;
    float o2 = y2 * c1 - y3 * s1;
    float o3 = y2 * s1 + y3 * c1;
    ((float4*)(out + (size_t)s * DIM))[t] = make_float4(o0, o1, o2, o3);
}

// ---------------- tf32 flash attention (BQ=128, BK=64) ----------------
#define ATT_SMEM_WORDS (128 * 128 + 64 * 128 + 128 * 64)
#define ATT_SMEM_BYTES (ATT_SMEM_WORDS * 4)

__global__ __launch_bounds__(256, 1) void attn_tf32(const float* __restrict__ RQ,
                                                    const float* __restrict__ RK,
                                                    const float* __restrict__ V,
                                                    float* __restrict__ O, int S) {
    extern __shared__ uint32_t sm[];
    uint32_t* Qs  = sm;                        // 128 x 128
    uint32_t* KVs = sm + 128 * 128;            // 64 x 128
    uint32_t* Ps  = sm + 128 * 128 + 64 * 128; // 128 x 64
    const int tid = threadIdx.x, lane = tid & 31, warp = tid >> 5;
    const int q = lane & 3, g2 = lane >> 2;
    const int head = blockIdx.y;
    const int qbase = blockIdx.x * 128;
    const float scale = 0.08838834764831845f;

    // Q tile (pre-scaled)
#pragma unroll
    for (int it = 0; it < 16; it++) {
        int f = tid + it * 256;
        int fg = f & 31, r = f >> 5;
        float4 v = make_float4(0, 0, 0, 0);
        if (qbase + r < S) v = *(const float4*)(RQ + (size_t)(qbase + r) * DIM + head * HD + fg * 4);
        uint4 t;
        t.x = f2tf(v.x * scale); t.y = f2tf(v.y * scale);
        t.z = f2tf(v.z * scale); t.w = f2tf(v.w * scale);
        *(uint4*)(Qs + r * 128 + ((fg * 4) & ~31) + (((fg ^ r) & 7) << 2)) = t;
    }

    float o[16][4];
    float mrow[2], lrow[2];
#pragma unroll
    for (int i = 0; i < 16; i++)
#pragma unroll
        for (int j = 0; j < 4; j++) o[i][j] = 0.f;
    mrow[0] = mrow[1] = -1e30f;
    lrow[0] = lrow[1] = 0.f;

    const int r0 = warp * 16 + g2;  // local Q row (also +8)
    const int nkt = (S + 63) >> 6;

    for (int kt = 0; kt < nkt; kt++) {
        const int kb = kt * 64;
        __syncthreads();
        // K tile
#pragma unroll
        for (int it = 0; it < 8; it++) {
            int f = tid + it * 256;
            int fg = f & 31, r = f >> 5;
            float4 v = make_float4(0, 0, 0, 0);
            if (kb + r < S) v = *(const float4*)(RK + (size_t)(kb + r) * DIM + head * HD + fg * 4);
            uint4 t;
            t.x = f2tf(v.x); t.y = f2tf(v.y); t.z = f2tf(v.z); t.w = f2tf(v.w);
            *(uint4*)(KVs + r * 128 + ((fg * 4) & ~31) + (((fg ^ r) & 7) << 2)) = t;
        }
        __syncthreads();
        // scores 16x64 per warp
        float sc[8][4];
#pragma unroll
        for (int nt = 0; nt < 8; nt++)
#pragma unroll
            for (int j = 0; j < 4; j++) sc[nt][j] = 0.f;
#pragma unroll
        for (int ks = 0; ks < 16; ks++) {
            int k0 = ks * 8;
            uint32_t a0 = Qs[r0 * 128 + sx(r0, k0 + q)];
            uint32_t a1 = Qs[(r0 + 8) * 128 + sx(r0 + 8, k0 + q)];
            uint32_t a2 = Qs[r0 * 128 + sx(r0, k0 + q + 4)];
            uint32_t a3 = Qs[(r0 + 8) * 128 + sx(r0 + 8, k0 + q + 4)];
#pragma unroll
            for (int nt = 0; nt < 8; nt++) {
                int n = nt * 8 + g2;
                uint32_t b0 = KVs[n * 128 + sx(n, k0 + q)];
                uint32_t b1 = KVs[n * 128 + sx(n, k0 + q + 4)];
                mma8(sc[nt], a0, a1, a2, a3, b0, b1);
            }
        }
        // online softmax per held row (half 0: row r0, half 1: row r0+8)
#pragma unroll
        for (int half = 0; half < 2; half++) {
            float tm = -1e30f;
#pragma unroll
            for (int nt = 0; nt < 8; nt++)
#pragma unroll
                for (int j = 0; j < 2; j++) {
                    int col = kb + nt * 8 + 2 * q + j;
                    float v = (col < S) ? sc[nt][half * 2 + j] : -1e30f;
                    sc[nt][half * 2 + j] = v;
                    tm = fmaxf(tm, v);
                }
            tm = fmaxf(tm, __shfl_xor_sync(~0u, tm, 1));
            tm = fmaxf(tm, __shfl_xor_sync(~0u, tm, 2));
            float mn = fmaxf(mrow[half], tm);
            float fct = __expf(mrow[half] - mn);
            mrow[half] = mn;
            float rs = 0.f;
            int rr = r0 + half * 8;
#pragma unroll
            for (int nt = 0; nt < 8; nt++)
#pragma unroll
                for (int j = 0; j < 2; j++) {
                    float p = __expf(sc[nt][half * 2 + j] - mn);
                    rs += p;
                    Ps[rr * 64 + sx(rr, nt * 8 + 2 * q + j)] = f2tf(p);
                }
            rs += __shfl_xor_sync(~0u, rs, 1);
            rs += __shfl_xor_sync(~0u, rs, 2);
            lrow[half] = lrow[half] * fct + rs;
#pragma unroll
            for (int nt2 = 0; nt2 < 16; nt2++) {
                o[nt2][half * 2] *= fct;
                o[nt2][half * 2 + 1] *= fct;
            }
        }
        __syncthreads();
        // V tile (reuse KVs)
#pragma unroll
        for (int it = 0; it < 8; it++) {
            int f = tid + it * 256;
            int fg = f & 31, r = f >> 5;
            float4 v = make_float4(0, 0, 0, 0);
            if (kb + r < S) v = *(const float4*)(V + (size_t)(kb + r) * DIM + head * HD + fg * 4);
            uint4 t;
            t.x = f2tf(v.x); t.y = f2tf(v.y); t.z = f2tf(v.z); t.w = f2tf(v.w);
            *(uint4*)(KVs + r * 128 + ((fg * 4) & ~31) + (((fg ^ r) & 7) << 2)) = t;
        }
        __syncthreads();
        // P @ V
#pragma unroll
        for (int ks = 0; ks < 8; ks++) {
            int k0 = ks * 8;
            uint32_t a0 = Ps[r0 * 64 + sx(r0, k0 + q)];
            uint32_t a1 = Ps[(r0 + 8) * 64 + sx(r0 + 8, k0 + q)];
            uint32_t a2 = Ps[r0 * 64 + sx(r0, k0 + q + 4)];
            uint32_t a3 = Ps[(r0 + 8) * 64 + sx(r0 + 8, k0 + q + 4)];
#pragma unroll
            for (int nt = 0; nt < 16; nt++) {
                int n = nt * 8 + g2;
                int kr = k0 + q;
                uint32_t b0 = KVs[kr * 128 + sx(kr, n)];
                uint32_t b1 = KVs[(kr + 4) * 128 + sx(kr + 4, n)];
                mma8(o[nt], a0, a1, a2, a3, b0, b1);
            }
        }
    }
    // epilogue
#pragma unroll
    for (int half = 0; half < 2; half++) {
        int r = qbase + r0 + half * 8;
        if (r < S) {
            float inv = 1.0f / lrow[half];
#pragma unroll
            for (int nt = 0; nt < 16; nt++) {
                O[(size_t)r * DIM + head * HD + nt * 8 + 2 * q]     = o[nt][half * 2] * inv;
                O[(size_t)r * DIM + head * HD + nt * 8 + 2 * q + 1] = o[nt][half * 2 + 1] * inv;
            }
        }
    }
}

// ---------------- M[n][d][j] = sum_m g_kv[n,d,m] * Wlin[j,m] ----------------
__global__ __launch_bounds__(256) void prepM_k(const float* __restrict__ g_kv,
                                               const float* __restrict__ Wlin) {
    int o = blockIdx.x * 256 + threadIdx.x;
    int n = o >> 14;
    int d = (o >> 7) & 127;
    int j = o & 127;
    const float* gp = g_kv + ((size_t)n * 128 + d) * 128;
    const float* wp = Wlin + (size_t)j * 128;
    float acc = 0.f;
#pragma unroll 8
    for (int mm = 0; mm < 128; mm++) acc += gp[mm] * wp[mm];
    g_M[o] = acc;
}

// ---------------- gated branch: att += z * (rq @ M_n) + blin ----------------
__global__ __launch_bounds__(128) void gated_k(const float* __restrict__ RQ,
                                               const float* __restrict__ blin,
                                               float* __restrict__ att) {
    const int s = blockIdx.x, n = blockIdx.y, j = threadIdx.x;
    __shared__ float rs[128];
    rs[j] = RQ[(size_t)s * DIM + n * HD + j];
    __syncthreads();
    const float* Mp = g_M + (size_t)n * (HD * HD) + j;
    float acc = 0.f;
#pragma unroll 16
    for (int d = 0; d < 128; d++) acc += rs[d] * Mp[(size_t)d * 128];
    const size_t idx = (size_t)s * DIM + n * HD + j;
    att[idx] += acc * g_z[s * NH + n] + blin[j];
}

// ---------------- host ----------------
extern "C" void kernel_launch(void* const* d_in, const int* in_sizes, int n_in,
                              void* d_out, int out_size) {
    const float* x       = (const float*)d_in[0];
    const float* freqs   = (const float*)d_in[1];
    const float* g_kmean = (const float*)d_in[2];
    const float* g_kv    = (const float*)d_in[3];
    const float* Wq = (const float*)d_in[4];  const float* bq = (const float*)d_in[5];
    const float* Wk = (const float*)d_in[6];  const float* bk = (const float*)d_in[7];
    const float* Wv = (const float*)d_in[8];  const float* bv = (const float*)d_in[9];
    const float* Wo = (const float*)d_in[10]; const float* bo = (const float*)d_in[11];
    const float* gq = (const float*)d_in[12]; const float* gk = (const float*)d_in[13];
    const float* Wlin = (const float*)d_in[14]; const float* blin = (const float*)d_in[15];
    const int* hG = (const int*)d_in[17];
    const int* wG = (const int*)d_in[18];
    float* out = (float*)d_out;

    int S = in_sizes[0] / DIM;
    if (S > S_MAX) S = S_MAX;

    cudaFuncSetAttribute(attn_tf32, cudaFuncAttributeMaxDynamicSharedMemorySize, ATT_SMEM_BYTES);

    float *qraw, *kraw, *vbuf, *rq, *rk, *att, *z;
    cudaGetSymbolAddress((void**)&qraw, g_qraw);
    cudaGetSymbolAddress((void**)&kraw, g_kraw);
    cudaGetSymbolAddress((void**)&vbuf, g_vbuf);
    cudaGetSymbolAddress((void**)&rq, g_rq);
    cudaGetSymbolAddress((void**)&rk, g_rk);
    cudaGetSymbolAddress((void**)&att, g_att);
    cudaGetSymbolAddress((void**)&z, g_z);

    dim3 gemmGrid((S + 127) / 128, DIM / 128);

    rope_table_k<<<S, 64>>>(freqs, hG, wG);
    gemm_tf32<<<gemmGrid, 256>>>(x, Wq, bq, qraw, S);
    gemm_tf32<<<gemmGrid, 256>>>(x, Wk, bk, kraw, S);
    gemm_tf32<<<gemmGrid, 256>>>(x, Wv, bv, vbuf, S);
    rmsrope_k<<<S, 384>>>(qraw, gq, g_kmean, rq, z, 1);
    rmsrope_k<<<S, 384>>>(kraw, gk, g_kmean, rk, z, 0);
    prepM_k<<<768, 256>>>(g_kv, Wlin);
    attn_tf32<<<dim3((S + 127) / 128, NH), 256, ATT_SMEM_BYTES>>>(rq, rk, vbuf, att, S);
    gated_k<<<dim3(S, NH), 128>>>(rq, blin, att);
    gemm_tf32<<<gemmGrid, 256>>>(att, Wo, bo, out, S);
}

// round 4
// speedup vs baseline: 3.9982x; 1.8641x over previous
#include <cuda_runtime.h>
#include <cuda_fp16.h>
#include <cstdint>

#define DIM 1536
#define NH 12
#define HD 128
#define S_MAX 4680

// ---------------- scratch ----------------
__device__ float g_qraw[S_MAX * DIM];
__device__ float g_kraw[S_MAX * DIM];
__device__ float g_vbuf[S_MAX * DIM];
__device__ __half g_rq[S_MAX * DIM];
__device__ __half g_rk[S_MAX * DIM];
__device__ float g_att[S_MAX * DIM];
__device__ float g_rope[S_MAX * HD];
__device__ float g_z[S_MAX * NH];
__device__ float g_M[NH * HD * HD];

// ---------------- helpers ----------------
__device__ __forceinline__ uint32_t smaddr(const void* p) {
    return (uint32_t)__cvta_generic_to_shared(p);
}
__device__ __forceinline__ void ldsm4(uint32_t* r, uint32_t a) {
    asm volatile("ldmatrix.sync.aligned.m8n8.x4.shared.b16 {%0,%1,%2,%3},[%4];"
                 : "=r"(r[0]), "=r"(r[1]), "=r"(r[2]), "=r"(r[3]) : "r"(a));
}
__device__ __forceinline__ void ldsm4t(uint32_t* r, uint32_t a) {
    asm volatile("ldmatrix.sync.aligned.m8n8.x4.trans.shared.b16 {%0,%1,%2,%3},[%4];"
                 : "=r"(r[0]), "=r"(r[1]), "=r"(r[2]), "=r"(r[3]) : "r"(a));
}
__device__ __forceinline__ void mma16(float* c, const uint32_t* a, uint32_t b0, uint32_t b1) {
    asm volatile(
        "mma.sync.aligned.m16n8k16.row.col.f32.f16.f16.f32 "
        "{%0,%1,%2,%3},{%4,%5,%6,%7},{%8,%9},{%0,%1,%2,%3};\n"
        : "+f"(c[0]), "+f"(c[1]), "+f"(c[2]), "+f"(c[3])
        : "r"(a[0]), "r"(a[1]), "r"(a[2]), "r"(a[3]), "r"(b0), "r"(b1));
}
__device__ __forceinline__ uint32_t packh2(float x, float y) {
    __half2 h = __floats2half2_rn(x, y);
    return *reinterpret_cast<uint32_t*>(&h);
}

// ---------------- rope table ----------------
__global__ void rope_table_k(const float* __restrict__ freqs,
                             const int* __restrict__ hg, const int* __restrict__ wg) {
    int s = blockIdx.x;
    int i = threadIdx.x;
    int h = hg[0], w = wg[0];
    int hw = h * w;
    int fi = s / hw;
    int rem = s - fi * hw;
    int hi = rem / w;
    int wi = rem - hi * w;
    int r = (i < 22) ? fi : ((i < 43) ? hi : wi);
    float2 v = ((const float2*)freqs)[r * 64 + i];
    ((float2*)g_rope)[s * 64 + i] = v;
}

// ---------------- fp16 NT GEMM: C[M,1536] = A * B^T + bias ----------------
__global__ __launch_bounds__(256, 2) void gemm_f16(const float* __restrict__ A,
                                                   const float* __restrict__ B,
                                                   const float* __restrict__ bias,
                                                   float* __restrict__ C, int M) {
    __shared__ __align__(16) __half As[128 * 64];
    __shared__ __align__(16) __half Bs[128 * 64];
    const int tid = threadIdx.x, lane = tid & 31, warp = tid >> 5;
    const int wm = warp >> 2, wn = warp & 3, q = lane & 3, g2 = lane >> 2;
    const int quad = lane >> 3, l7 = lane & 7;
    const int mbase = blockIdx.x * 128, nbase = blockIdx.y * 128;
    const uint32_t asb = smaddr(As), bsb = smaddr(Bs);

    float acc[4][4][4];
#pragma unroll
    for (int i = 0; i < 4; i++)
#pragma unroll
        for (int j = 0; j < 4; j++)
#pragma unroll
            for (int k = 0; k < 4; k++) acc[i][j][k] = 0.f;

    for (int kt = 0; kt < DIM; kt += 64) {
        __syncthreads();
#pragma unroll
        for (int it = 0; it < 4; it++) {
            int idx = tid + it * 256;
            int r = idx >> 3, c = idx & 7;
            float4 a0 = make_float4(0, 0, 0, 0), a1 = a0;
            if (mbase + r < M) {
                const float* p = A + (size_t)(mbase + r) * DIM + kt + c * 8;
                a0 = *(const float4*)p; a1 = *(const float4*)(p + 4);
            }
            uint4 av;
            av.x = packh2(a0.x, a0.y); av.y = packh2(a0.z, a0.w);
            av.z = packh2(a1.x, a1.y); av.w = packh2(a1.z, a1.w);
            *(uint4*)((char*)As + r * 128 + ((c ^ (r & 7)) << 4)) = av;
            const float* pb = B + (size_t)(nbase + r) * DIM + kt + c * 8;
            float4 b0 = *(const float4*)pb, b1 = *(const float4*)(pb + 4);
            uint4 bv;
            bv.x = packh2(b0.x, b0.y); bv.y = packh2(b0.z, b0.w);
            bv.z = packh2(b1.x, b1.y); bv.w = packh2(b1.z, b1.w);
            *(uint4*)((char*)Bs + r * 128 + ((c ^ (r & 7)) << 4)) = bv;
        }
        __syncthreads();
#pragma unroll
        for (int ks = 0; ks < 4; ks++) {
            uint32_t af[4][4];
#pragma unroll
            for (int mt = 0; mt < 4; mt++) {
                int row = wm * 64 + mt * 16 + ((quad & 1) << 3) + l7;
                int c = ks * 2 + (quad >> 1);
                ldsm4(af[mt], asb + row * 128 + ((c ^ (row & 7)) << 4));
            }
#pragma unroll
            for (int nb = 0; nb < 2; nb++) {
                uint32_t bf[4];
                int n = wn * 32 + nb * 16 + ((quad >> 1) << 3) + l7;
                int c = ks * 2 + (quad & 1);
                ldsm4(bf, bsb + n * 128 + ((c ^ (n & 7)) << 4));
#pragma unroll
                for (int mt = 0; mt < 4; mt++) {
                    mma16(acc[mt][nb * 2], af[mt], bf[0], bf[1]);
                    mma16(acc[mt][nb * 2 + 1], af[mt], bf[2], bf[3]);
                }
            }
        }
    }
#pragma unroll
    for (int mt = 0; mt < 4; mt++) {
        int r0 = mbase + wm * 64 + mt * 16 + g2;
#pragma unroll
        for (int nt = 0; nt < 4; nt++) {
            int c0 = nbase + wn * 32 + nt * 8 + 2 * q;
            if (r0 < M) {
                C[(size_t)r0 * DIM + c0]     = acc[mt][nt][0] + bias[c0];
                C[(size_t)r0 * DIM + c0 + 1] = acc[mt][nt][1] + bias[c0 + 1];
            }
            if (r0 + 8 < M) {
                C[(size_t)(r0 + 8) * DIM + c0]     = acc[mt][nt][2] + bias[c0];
                C[(size_t)(r0 + 8) * DIM + c0 + 1] = acc[mt][nt][3] + bias[c0 + 1];
            }
        }
    }
}

// ---------------- RMS + RoPE + optional z ; fp16 output with prescale ----------------
__global__ __launch_bounds__(384) void rmsrope_k(const float* __restrict__ in,
                                                 const float* __restrict__ g,
                                                 const float* __restrict__ gkm,
                                                 __half* __restrict__ out,
                                                 float* __restrict__ zout, int doZ,
                                                 float prescale) {
    const int s = blockIdx.x;
    const int t = threadIdx.x;
    const int warp = t >> 5, lane = t & 31;
    float4 v = ((const float4*)(in + (size_t)s * DIM))[t];
    float ss = v.x * v.x + v.y * v.y + v.z * v.z + v.w * v.w;
#pragma unroll
    for (int off = 16; off; off >>= 1) ss += __shfl_xor_sync(~0u, ss, off);
    __shared__ float red[12];
    __shared__ float sinv;
    if (lane == 0) red[warp] = ss;
    __syncthreads();
    if (t == 0) {
        float tot = 0;
#pragma unroll
        for (int i = 0; i < 12; i++) tot += red[i];
        sinv = rsqrtf(tot * (1.0f / DIM) + 1e-6f);
    }
    __syncthreads();
    const float inv = sinv;
    const int e = t * 4;
    float y0 = v.x * inv * g[e + 0];
    float y1 = v.y * inv * g[e + 1];
    float y2 = v.z * inv * g[e + 2];
    float y3 = v.w * inv * g[e + 3];
    if (doZ) {
        float zp = fmaxf(y0, 0.f) * gkm[e + 0] + fmaxf(y1, 0.f) * gkm[e + 1] +
                   fmaxf(y2, 0.f) * gkm[e + 2] + fmaxf(y3, 0.f) * gkm[e + 3];
#pragma unroll
        for (int off = 16; off; off >>= 1) zp += __shfl_xor_sync(~0u, zp, off);
        if (lane == 0) zout[s * NH + warp] = 1.0f / (zp + 1e-6f);
    }
    const int i0 = (2 * t) & 63;
    const float* rp = g_rope + (size_t)s * HD + i0 * 2;
    float c0 = rp[0], s0 = rp[1], c1 = rp[2], s1 = rp[3];
    float o0 = (y0 * c0 - y1 * s0) * prescale;
    float o1 = (y0 * s0 + y1 * c0) * prescale;
    float o2 = (y2 * c1 - y3 * s1) * prescale;
    float o3 = (y2 * s1 + y3 * c1) * prescale;
    __half2* op = (__half2*)(out + (size_t)s * DIM);
    op[t * 2]     = __floats2half2_rn(o0, o1);
    op[t * 2 + 1] = __floats2half2_rn(o2, o3);
}

// ---------------- fp16 flash attention (BQ=128, BK=64) ----------------
#define ATT_SMEM_BYTES ((128 * 128 + 64 * 128 + 128 * 64) * 2)

__global__ __launch_bounds__(256, 1) void attn_f16(const __half* __restrict__ RQ,
                                                   const __half* __restrict__ RK,
                                                   const float* __restrict__ V,
                                                   float* __restrict__ O, int S) {
    extern __shared__ __align__(16) __half smh[];
    __half* Qs  = smh;                       // 128 x 128 (256B rows)
    __half* KVs = smh + 128 * 128;           // 64 x 128 (256B rows)
    __half* Ps  = smh + 128 * 128 + 64 * 128;// 128 x 64 (128B rows)
    const uint32_t qsb = smaddr(Qs), kvb = smaddr(KVs), psb = smaddr(Ps);
    const int tid = threadIdx.x, lane = tid & 31, warp = tid >> 5;
    const int q = lane & 3, g2 = lane >> 2, quad = lane >> 3, l7 = lane & 7;
    const int head = blockIdx.y;
    const int qbase = blockIdx.x * 128;

    // Q tile (fp16 in gmem already; K carries the 1/sqrt(d) prescale)
#pragma unroll
    for (int it = 0; it < 8; it++) {
        int idx = tid + it * 256;
        int r = idx >> 4, c = idx & 15;
        uint4 v = make_uint4(0, 0, 0, 0);
        if (qbase + r < S) v = *(const uint4*)(RQ + (size_t)(qbase + r) * DIM + head * HD + c * 8);
        int cp = (c & 8) | ((c ^ (r & 7)) & 7);
        *(uint4*)((char*)Qs + r * 256 + (cp << 4)) = v;
    }

    float o[16][4];
    float mrow[2], lrow[2];
#pragma unroll
    for (int i = 0; i < 16; i++)
#pragma unroll
        for (int j = 0; j < 4; j++) o[i][j] = 0.f;
    mrow[0] = mrow[1] = -1e30f;
    lrow[0] = lrow[1] = 0.f;

    const int r0 = warp * 16 + g2;
    const int nkt = (S + 63) >> 6;

    for (int kt = 0; kt < nkt; kt++) {
        const int kb = kt * 64;
        __syncthreads();
        // K tile
#pragma unroll
        for (int it = 0; it < 4; it++) {
            int idx = tid + it * 256;
            int r = idx >> 4, c = idx & 15;
            uint4 v = make_uint4(0, 0, 0, 0);
            if (kb + r < S) v = *(const uint4*)(RK + (size_t)(kb + r) * DIM + head * HD + c * 8);
            int cp = (c & 8) | ((c ^ (r & 7)) & 7);
            *(uint4*)((char*)KVs + r * 256 + (cp << 4)) = v;
        }
        __syncthreads();
        // QK^T : per warp 16 rows x 64 cols
        float sc[8][4];
#pragma unroll
        for (int nt = 0; nt < 8; nt++)
#pragma unroll
            for (int j = 0; j < 4; j++) sc[nt][j] = 0.f;
#pragma unroll
        for (int ks = 0; ks < 8; ks++) {
            uint32_t af[4];
            {
                int row = warp * 16 + ((quad & 1) << 3) + l7;
                int c = ks * 2 + (quad >> 1);
                int cp = (c & 8) | ((c ^ (row & 7)) & 7);
                ldsm4(af, qsb + row * 256 + (cp << 4));
            }
#pragma unroll
            for (int nb = 0; nb < 4; nb++) {
                uint32_t bf[4];
                int n = nb * 16 + ((quad >> 1) << 3) + l7;
                int c = ks * 2 + (quad & 1);
                int cp = (c & 8) | ((c ^ (n & 7)) & 7);
                ldsm4(bf, kvb + n * 256 + (cp << 4));
                mma16(sc[nb * 2], af, bf[0], bf[1]);
                mma16(sc[nb * 2 + 1], af, bf[2], bf[3]);
            }
        }
        // online softmax
#pragma unroll
        for (int hf = 0; hf < 2; hf++) {
            float tm = -1e30f;
#pragma unroll
            for (int nt = 0; nt < 8; nt++)
#pragma unroll
                for (int j = 0; j < 2; j++) {
                    int col = kb + nt * 8 + 2 * q + j;
                    float v = (col < S) ? sc[nt][hf * 2 + j] : -1e30f;
                    sc[nt][hf * 2 + j] = v;
                    tm = fmaxf(tm, v);
                }
            tm = fmaxf(tm, __shfl_xor_sync(~0u, tm, 1));
            tm = fmaxf(tm, __shfl_xor_sync(~0u, tm, 2));
            float mn = fmaxf(mrow[hf], tm);
            float fct = __expf(mrow[hf] - mn);
            mrow[hf] = mn;
            float rs = 0.f;
            int rr = r0 + hf * 8;
#pragma unroll
            for (int nt = 0; nt < 8; nt++)
#pragma unroll
                for (int j = 0; j < 2; j++) {
                    float p = __expf(sc[nt][hf * 2 + j] - mn);
                    rs += p;
                    *((__half*)((char*)Ps + rr * 128 + ((nt ^ (rr & 7)) << 4) + (2 * q + j) * 2)) =
                        __float2half(p);
                }
            rs += __shfl_xor_sync(~0u, rs, 1);
            rs += __shfl_xor_sync(~0u, rs, 2);
            lrow[hf] = lrow[hf] * fct + rs;
#pragma unroll
            for (int nt2 = 0; nt2 < 16; nt2++) {
                o[nt2][hf * 2] *= fct;
                o[nt2][hf * 2 + 1] *= fct;
            }
        }
        __syncthreads();
        // V tile (fp32 -> fp16)
#pragma unroll
        for (int it = 0; it < 4; it++) {
            int idx = tid + it * 256;
            int r = idx >> 4, c = idx & 15;
            float4 v0 = make_float4(0, 0, 0, 0), v1 = v0;
            if (kb + r < S) {
                const float* p = V + (size_t)(kb + r) * DIM + head * HD + c * 8;
                v0 = *(const float4*)p; v1 = *(const float4*)(p + 4);
            }
            uint4 hv;
            hv.x = packh2(v0.x, v0.y); hv.y = packh2(v0.z, v0.w);
            hv.z = packh2(v1.x, v1.y); hv.w = packh2(v1.z, v1.w);
            int cp = (c & 8) | ((c ^ (r & 7)) & 7);
            *(uint4*)((char*)KVs + r * 256 + (cp << 4)) = hv;
        }
        __syncthreads();
        // P @ V  (V loaded transposed via ldmatrix.trans)
#pragma unroll
        for (int ks = 0; ks < 4; ks++) {
            uint32_t af[4];
            {
                int row = warp * 16 + ((quad & 1) << 3) + l7;
                int c = ks * 2 + (quad >> 1);
                ldsm4(af, psb + row * 128 + ((c ^ (row & 7)) << 4));
            }
#pragma unroll
            for (int nb = 0; nb < 8; nb++) {
                uint32_t bf[4];
                int row = ks * 16 + ((quad & 1) << 3) + l7;   // token row
                int c = nb * 2 + (quad >> 1);                 // dim chunk
                int cp = (c & 8) | ((c ^ (row & 7)) & 7);
                ldsm4t(bf, kvb + row * 256 + (cp << 4));
                mma16(o[nb * 2], af, bf[0], bf[1]);
                mma16(o[nb * 2 + 1], af, bf[2], bf[3]);
            }
        }
    }
    // epilogue
#pragma unroll
    for (int hf = 0; hf < 2; hf++) {
        int r = qbase + r0 + hf * 8;
        if (r < S) {
            float inv = 1.0f / lrow[hf];
#pragma unroll
            for (int nt = 0; nt < 16; nt++) {
                O[(size_t)r * DIM + head * HD + nt * 8 + 2 * q]     = o[nt][hf * 2] * inv;
                O[(size_t)r * DIM + head * HD + nt * 8 + 2 * q + 1] = o[nt][hf * 2 + 1] * inv;
            }
        }
    }
}

// ---------------- M[n][d][j] = sum_m g_kv[n,d,m] * Wlin[j,m] ----------------
__global__ __launch_bounds__(256) void prepM_k(const float* __restrict__ g_kv,
                                               const float* __restrict__ Wlin) {
    int o = blockIdx.x * 256 + threadIdx.x;
    int n = o >> 14;
    int d = (o >> 7) & 127;
    int j = o & 127;
    const float* gp = g_kv + ((size_t)n * 128 + d) * 128;
    const float* wp = Wlin + (size_t)j * 128;
    float acc = 0.f;
#pragma unroll 8
    for (int mm = 0; mm < 128; mm++) acc += gp[mm] * wp[mm];
    g_M[o] = acc;
}

// ---------------- gated branch: att += z * (rq @ M_n) + blin ----------------
__global__ __launch_bounds__(128) void gated_k(const __half* __restrict__ RQ,
                                               const float* __restrict__ blin,
                                               float* __restrict__ att) {
    const int s = blockIdx.x, n = blockIdx.y, j = threadIdx.x;
    __shared__ float rs[128];
    rs[j] = __half2float(RQ[(size_t)s * DIM + n * HD + j]);
    __syncthreads();
    const float* Mp = g_M + (size_t)n * (HD * HD) + j;
    float acc = 0.f;
#pragma unroll 16
    for (int d = 0; d < 128; d++) acc += rs[d] * Mp[(size_t)d * 128];
    const size_t idx = (size_t)s * DIM + n * HD + j;
    att[idx] += acc * g_z[s * NH + n] + blin[j];
}

// ---------------- host ----------------
extern "C" void kernel_launch(void* const* d_in, const int* in_sizes, int n_in,
                              void* d_out, int out_size) {
    const float* x       = (const float*)d_in[0];
    const float* freqs   = (const float*)d_in[1];
    const float* g_kmean = (const float*)d_in[2];
    const float* g_kv    = (const float*)d_in[3];
    const float* Wq = (const float*)d_in[4];  const float* bq = (const float*)d_in[5];
    const float* Wk = (const float*)d_in[6];  const float* bk = (const float*)d_in[7];
    const float* Wv = (const float*)d_in[8];  const float* bv = (const float*)d_in[9];
    const float* Wo = (const float*)d_in[10]; const float* bo = (const float*)d_in[11];
    const float* gq = (const float*)d_in[12]; const float* gk = (const float*)d_in[13];
    const float* Wlin = (const float*)d_in[14]; const float* blin = (const float*)d_in[15];
    const int* hG = (const int*)d_in[17];
    const int* wG = (const int*)d_in[18];
    float* out = (float*)d_out;

    int S = in_sizes[0] / DIM;
    if (S > S_MAX) S = S_MAX;

    cudaFuncSetAttribute(attn_f16, cudaFuncAttributeMaxDynamicSharedMemorySize, ATT_SMEM_BYTES);

    float *qraw, *kraw, *vbuf, *att, *z;
    __half *rq, *rk;
    cudaGetSymbolAddress((void**)&qraw, g_qraw);
    cudaGetSymbolAddress((void**)&kraw, g_kraw);
    cudaGetSymbolAddress((void**)&vbuf, g_vbuf);
    cudaGetSymbolAddress((void**)&rq, g_rq);
    cudaGetSymbolAddress((void**)&rk, g_rk);
    cudaGetSymbolAddress((void**)&att, g_att);
    cudaGetSymbolAddress((void**)&z, g_z);

    dim3 gemmGrid((S + 127) / 128, DIM / 128);
    const float scale = 0.08838834764831845f;

    rope_table_k<<<S, 64>>>(freqs, hG, wG);
    gemm_f16<<<gemmGrid, 256>>>(x, Wq, bq, qraw, S);
    gemm_f16<<<gemmGrid, 256>>>(x, Wk, bk, kraw, S);
    gemm_f16<<<gemmGrid, 256>>>(x, Wv, bv, vbuf, S);
    rmsrope_k<<<S, 384>>>(qraw, gq, g_kmean, rq, z, 1, 1.0f);
    rmsrope_k<<<S, 384>>>(kraw, gk, g_kmean, rk, z, 0, scale);
    prepM_k<<<768, 256>>>(g_kv, Wlin);
    attn_f16<<<dim3((S + 127) / 128, NH), 256, ATT_SMEM_BYTES>>>(rq, rk, vbuf, att, S);
    gated_k<<<dim3(S, NH), 128>>>(rq, blin, att);
    gemm_f16<<<gemmGrid, 256>>>(att, Wo, bo, out, S);
}

// round 6
// speedup vs baseline: 5.8441x; 1.4617x over previous
#include <cuda_runtime.h>
#include <cuda_fp16.h>
#include <cstdint>

#define DIM 1536
#define NH 12
#define HD 128
#define S_MAX 4680

// ---------------- scratch ----------------
__device__ float  g_qraw[S_MAX * DIM];
__device__ float  g_kraw[S_MAX * DIM];
__device__ float  g_att[S_MAX * DIM];
__device__ __half g_xh[S_MAX * DIM];
__device__ __half g_vh[S_MAX * DIM];
__device__ __half g_atth[S_MAX * DIM];
__device__ __half g_rq[S_MAX * DIM];
__device__ __half g_rk[S_MAX * DIM];
__device__ __half g_wqh[DIM * DIM];
__device__ __half g_wkh[DIM * DIM];
__device__ __half g_wvh[DIM * DIM];
__device__ __half g_woh[DIM * DIM];
__device__ float  g_rope[S_MAX * HD];
__device__ float  g_z[S_MAX * NH];
__device__ float  g_M[NH * HD * HD];

// ---------------- helpers ----------------
__device__ __forceinline__ uint32_t smaddr(const void* p) {
    return (uint32_t)__cvta_generic_to_shared(p);
}
__device__ __forceinline__ void ldsm4(uint32_t* r, uint32_t a) {
    asm volatile("ldmatrix.sync.aligned.m8n8.x4.shared.b16 {%0,%1,%2,%3},[%4];"
                 : "=r"(r[0]), "=r"(r[1]), "=r"(r[2]), "=r"(r[3]) : "r"(a));
}
__device__ __forceinline__ void ldsm4t(uint32_t* r, uint32_t a) {
    asm volatile("ldmatrix.sync.aligned.m8n8.x4.trans.shared.b16 {%0,%1,%2,%3},[%4];"
                 : "=r"(r[0]), "=r"(r[1]), "=r"(r[2]), "=r"(r[3]) : "r"(a));
}
__device__ __forceinline__ void mma16(float* c, const uint32_t* a, uint32_t b0, uint32_t b1) {
    asm volatile(
        "mma.sync.aligned.m16n8k16.row.col.f32.f16.f16.f32 "
        "{%0,%1,%2,%3},{%4,%5,%6,%7},{%8,%9},{%0,%1,%2,%3};\n"
        : "+f"(c[0]), "+f"(c[1]), "+f"(c[2]), "+f"(c[3])
        : "r"(a[0]), "r"(a[1]), "r"(a[2]), "r"(a[3]), "r"(b0), "r"(b1));
}
__device__ __forceinline__ uint32_t packh2(float x, float y) {
    __half2 h = __floats2half2_rn(x, y);
    return *reinterpret_cast<uint32_t*>(&h);
}
__device__ __forceinline__ void cpa16(uint32_t dst, const void* src, int sb) {
    asm volatile("cp.async.cg.shared.global [%0], [%1], 16, %2;" :: "r"(dst), "l"(src), "r"(sb));
}
#define CP_COMMIT() asm volatile("cp.async.commit_group;" ::: "memory")
#define CP_WAIT1()  asm volatile("cp.async.wait_group 1;" ::: "memory")

// ---------------- fp32 -> fp16 convert ----------------
__global__ void conv_h(const float* __restrict__ src, __half* __restrict__ dst, int n4) {
    int i = blockIdx.x * 256 + threadIdx.x;
    if (i < n4) {
        float4 v = ((const float4*)src)[i];
        ((__half2*)dst)[2 * i]     = __floats2half2_rn(v.x, v.y);
        ((__half2*)dst)[2 * i + 1] = __floats2half2_rn(v.z, v.w);
    }
}

// ---------------- rope table ----------------
__global__ void rope_table_k(const float* __restrict__ freqs,
                             const int* __restrict__ hg, const int* __restrict__ wg) {
    int s = blockIdx.x;
    int i = threadIdx.x;
    int h = hg[0], w = wg[0];
    int hw = h * w;
    int fi = s / hw;
    int rem = s - fi * hw;
    int hi = rem / w;
    int wi = rem - hi * w;
    int r = (i < 22) ? fi : ((i < 43) ? hi : wi);
    float2 v = ((const float2*)freqs)[r * 64 + i];
    ((float2*)g_rope)[s * 64 + i] = v;
}

// ---------------- fp16 NT GEMM with cp.async 2-stage: C = A * B^T + bias ----------------
#define GEMM_SMEM_BYTES (4 * 128 * 64 * 2)  // 2 stages x (A+B) x 16KB = 64KB

__global__ __launch_bounds__(256, 2) void gemm_h(const __half* __restrict__ A,
                                                 const __half* __restrict__ B,
                                                 const float* __restrict__ bias,
                                                 float* __restrict__ C,
                                                 __half* __restrict__ Ch, int M) {
    extern __shared__ __align__(16) __half gsm[];
    __half* As = gsm;                    // [2][128*64]
    __half* Bs = gsm + 2 * 128 * 64;     // [2][128*64]
    const uint32_t asb = smaddr(As), bsb = smaddr(Bs);
    const int tid = threadIdx.x, lane = tid & 31, warp = tid >> 5;
    const int wm = warp >> 2, wn = warp & 3, q = lane & 3, g2 = lane >> 2;
    const int quad = lane >> 3, l7 = lane & 7;
    const int mbase = blockIdx.x * 128, nbase = blockIdx.y * 128;
    const int NK = DIM / 64;  // 24

    float acc[4][4][4];
#pragma unroll
    for (int i = 0; i < 4; i++)
#pragma unroll
        for (int j = 0; j < 4; j++)
#pragma unroll
            for (int k = 0; k < 4; k++) acc[i][j][k] = 0.f;

    auto issue = [&](int s) {
        if (s < NK) {
            int k0 = s * 64;
            uint32_t ad = asb + (s & 1) * 16384;
            uint32_t bd = bsb + (s & 1) * 16384;
#pragma unroll
            for (int it = 0; it < 4; it++) {
                int idx = tid + it * 256;
                int r = idx >> 3, c = idx & 7;
                int off = r * 128 + ((c ^ (r & 7)) << 4);
                int arow = mbase + r;
                int ar = arow < M ? arow : M - 1;
                cpa16(ad + off, A + (size_t)ar * DIM + k0 + c * 8, arow < M ? 16 : 0);
                cpa16(bd + off, B + (size_t)(nbase + r) * DIM + k0 + c * 8, 16);
            }
        }
        CP_COMMIT();
    };

    issue(0);
    issue(1);

    for (int kt = 0; kt < NK; kt++) {
        CP_WAIT1();
        __syncthreads();
        uint32_t ab = asb + (kt & 1) * 16384;
        uint32_t bb = bsb + (kt & 1) * 16384;
#pragma unroll
        for (int ks = 0; ks < 4; ks++) {
            uint32_t af[4][4];
#pragma unroll
            for (int mt = 0; mt < 4; mt++) {
                int row = wm * 64 + mt * 16 + ((quad & 1) << 3) + l7;
                int c = ks * 2 + (quad >> 1);
                ldsm4(af[mt], ab + row * 128 + ((c ^ (row & 7)) << 4));
            }
#pragma unroll
            for (int nb = 0; nb < 2; nb++) {
                uint32_t bf[4];
                int n = wn * 32 + nb * 16 + ((quad >> 1) << 3) + l7;
                int c = ks * 2 + (quad & 1);
                ldsm4(bf, bb + n * 128 + ((c ^ (n & 7)) << 4));
#pragma unroll
                for (int mt = 0; mt < 4; mt++) {
                    mma16(acc[mt][nb * 2], af[mt], bf[0], bf[1]);
                    mma16(acc[mt][nb * 2 + 1], af[mt], bf[2], bf[3]);
                }
            }
        }
        __syncthreads();
        issue(kt + 2);
    }
#pragma unroll
    for (int mt = 0; mt < 4; mt++) {
        int r0 = mbase + wm * 64 + mt * 16 + g2;
#pragma unroll
        for (int nt = 0; nt < 4; nt++) {
            int c0 = nbase + wn * 32 + nt * 8 + 2 * q;
            float v0 = acc[mt][nt][0] + bias[c0];
            float v1 = acc[mt][nt][1] + bias[c0 + 1];
            float v2 = acc[mt][nt][2] + bias[c0];
            float v3 = acc[mt][nt][3] + bias[c0 + 1];
            if (Ch) {
                if (r0 < M)
                    *(__half2*)(Ch + (size_t)r0 * DIM + c0) = __floats2half2_rn(v0, v1);
                if (r0 + 8 < M)
                    *(__half2*)(Ch + (size_t)(r0 + 8) * DIM + c0) = __floats2half2_rn(v2, v3);
            } else {
                if (r0 < M) {
                    C[(size_t)r0 * DIM + c0] = v0;
                    C[(size_t)r0 * DIM + c0 + 1] = v1;
                }
                if (r0 + 8 < M) {
                    C[(size_t)(r0 + 8) * DIM + c0] = v2;
                    C[(size_t)(r0 + 8) * DIM + c0 + 1] = v3;
                }
            }
        }
    }
}

// ---------------- RMS + RoPE + optional z ; fp16 output with prescale ----------------
__global__ __launch_bounds__(384) void rmsrope_k(const float* __restrict__ in,
                                                 const float* __restrict__ g,
                                                 const float* __restrict__ gkm,
                                                 __half* __restrict__ out,
                                                 float* __restrict__ zout, int doZ,
                                                 float prescale) {
    const int s = blockIdx.x;
    const int t = threadIdx.x;
    const int warp = t >> 5, lane = t & 31;
    float4 v = ((const float4*)(in + (size_t)s * DIM))[t];
    float ss = v.x * v.x + v.y * v.y + v.z * v.z + v.w * v.w;
#pragma unroll
    for (int off = 16; off; off >>= 1) ss += __shfl_xor_sync(~0u, ss, off);
    __shared__ float red[12];
    __shared__ float sinv;
    if (lane == 0) red[warp] = ss;
    __syncthreads();
    if (t == 0) {
        float tot = 0;
#pragma unroll
        for (int i = 0; i < 12; i++) tot += red[i];
        sinv = rsqrtf(tot * (1.0f / DIM) + 1e-6f);
    }
    __syncthreads();
    const float inv = sinv;
    const int e = t * 4;
    float y0 = v.x * inv * g[e + 0];
    float y1 = v.y * inv * g[e + 1];
    float y2 = v.z * inv * g[e + 2];
    float y3 = v.w * inv * g[e + 3];
    if (doZ) {
        float zp = fmaxf(y0, 0.f) * gkm[e + 0] + fmaxf(y1, 0.f) * gkm[e + 1] +
                   fmaxf(y2, 0.f) * gkm[e + 2] + fmaxf(y3, 0.f) * gkm[e + 3];
#pragma unroll
        for (int off = 16; off; off >>= 1) zp += __shfl_xor_sync(~0u, zp, off);
        if (lane == 0) zout[s * NH + warp] = 1.0f / (zp + 1e-6f);
    }
    const int i0 = (2 * t) & 63;
    const float* rp = g_rope + (size_t)s * HD + i0 * 2;
    float c0 = rp[0], s0 = rp[1], c1 = rp[2], s1 = rp[3];
    float o0 = (y0 * c0 - y1 * s0) * prescale;
    float o1 = (y0 * s0 + y1 * c0) * prescale;
    float o2 = (y2 * c1 - y3 * s1) * prescale;
    float o3 = (y2 * s1 + y3 * c1) * prescale;
    __half2* op = (__half2*)(out + (size_t)s * DIM);
    op[t * 2]     = __floats2half2_rn(o0, o1);
    op[t * 2 + 1] = __floats2half2_rn(o2, o3);
}

// ---------------- fp16 flash attention: cp.async 2-stage K/V, register P ----------------
// smem: Q 128x128 (32KB) + K[2] 64x128 (32KB) + V[2] 64x128 (32KB) = 96KB
#define KS_BYTES 16384
#define ATT_SMEM_BYTES ((128 * 128 + 4 * 64 * 128) * 2)

__global__ __launch_bounds__(256, 1) void attn_f16(const __half* __restrict__ RQ,
                                                   const __half* __restrict__ RK,
                                                   const __half* __restrict__ V,
                                                   float* __restrict__ O, int S) {
    extern __shared__ __align__(16) __half smh[];
    __half* Qs = smh;                         // 128 x 128
    __half* Ks = smh + 128 * 128;             // [2] x 64 x 128
    __half* Vs = smh + 128 * 128 + 2 * 64 * 128;
    const uint32_t qsb = smaddr(Qs), ksb = smaddr(Ks), vsb = smaddr(Vs);
    const int tid = threadIdx.x, lane = tid & 31, warp = tid >> 5;
    const int q = lane & 3, g2 = lane >> 2, quad = lane >> 3, l7 = lane & 7;
    const int head = blockIdx.y;
    const int qbase = blockIdx.x * 128;
    const int nkt = (S + 63) >> 6;

    // Q tile
#pragma unroll
    for (int it = 0; it < 8; it++) {
        int idx = tid + it * 256;
        int r = idx >> 4, c = idx & 15;
        uint4 v = make_uint4(0, 0, 0, 0);
        if (qbase + r < S) v = *(const uint4*)(RQ + (size_t)(qbase + r) * DIM + head * HD + c * 8);
        int cp = (c & 8) | ((c ^ (r & 7)) & 7);
        *(uint4*)((char*)Qs + r * 256 + (cp << 4)) = v;
    }

    auto issue = [&](int s) {
        if (s < nkt) {
            int kb = s * 64;
            uint32_t kd = ksb + (s & 1) * KS_BYTES;
            uint32_t vd = vsb + (s & 1) * KS_BYTES;
#pragma unroll
            for (int it = 0; it < 4; it++) {
                int idx = tid + it * 256;
                int r = idx >> 4, c = idx & 15;
                int row = kb + r;
                int rc = row < S ? row : S - 1;
                int sb = row < S ? 16 : 0;
                int cp = (c & 8) | ((c ^ (r & 7)) & 7);
                int off = r * 256 + (cp << 4);
                const size_t go = (size_t)rc * DIM + head * HD + c * 8;
                cpa16(kd + off, RK + go, sb);
                cpa16(vd + off, V + go, sb);
            }
        }
        CP_COMMIT();
    };
    issue(0);
    issue(1);
    __syncthreads();

    // hoist Q fragments
    uint32_t qf[8][4];
#pragma unroll
    for (int ks = 0; ks < 8; ks++) {
        int row = warp * 16 + ((quad & 1) << 3) + l7;
        int c = ks * 2 + (quad >> 1);
        int cp = (c & 8) | ((c ^ (row & 7)) & 7);
        ldsm4(qf[ks], qsb + row * 256 + (cp << 4));
    }

    float o[16][4];
    float mrow[2], lrow[2];
#pragma unroll
    for (int i = 0; i < 16; i++)
#pragma unroll
        for (int j = 0; j < 4; j++) o[i][j] = 0.f;
    mrow[0] = mrow[1] = -1e30f;
    lrow[0] = lrow[1] = 0.f;

    for (int kt = 0; kt < nkt; kt++) {
        const int kb = kt * 64;
        CP_WAIT1();
        __syncthreads();
        const uint32_t kbb = ksb + (kt & 1) * KS_BYTES;
        const uint32_t vbb = vsb + (kt & 1) * KS_BYTES;

        // QK^T (log2-domain; K pre-scaled by 128^-.5*log2e)
        float sc[8][4];
#pragma unroll
        for (int nt = 0; nt < 8; nt++)
#pragma unroll
            for (int j = 0; j < 4; j++) sc[nt][j] = 0.f;
#pragma unroll
        for (int ks = 0; ks < 8; ks++) {
#pragma unroll
            for (int nb = 0; nb < 4; nb++) {
                uint32_t bf[4];
                int n = nb * 16 + ((quad >> 1) << 3) + l7;
                int c = ks * 2 + (quad & 1);
                int cp = (c & 8) | ((c ^ (n & 7)) & 7);
                ldsm4(bf, kbb + n * 256 + (cp << 4));
                mma16(sc[nb * 2], qf[ks], bf[0], bf[1]);
                mma16(sc[nb * 2 + 1], qf[ks], bf[2], bf[3]);
            }
        }
        // online softmax (exp2); sc becomes P
        float fct[2];
#pragma unroll
        for (int hf = 0; hf < 2; hf++) {
            float tm = -1e30f;
#pragma unroll
            for (int nt = 0; nt < 8; nt++)
#pragma unroll
                for (int j = 0; j < 2; j++) {
                    int col = kb + nt * 8 + 2 * q + j;
                    float v = (col < S) ? sc[nt][hf * 2 + j] : -1e30f;
                    sc[nt][hf * 2 + j] = v;
                    tm = fmaxf(tm, v);
                }
            tm = fmaxf(tm, __shfl_xor_sync(~0u, tm, 1));
            tm = fmaxf(tm, __shfl_xor_sync(~0u, tm, 2));
            float mn = fmaxf(mrow[hf], tm);
            fct[hf] = exp2f(mrow[hf] - mn);
            mrow[hf] = mn;
            float rs = 0.f;
#pragma unroll
            for (int nt = 0; nt < 8; nt++)
#pragma unroll
                for (int j = 0; j < 2; j++) {
                    float p = exp2f(sc[nt][hf * 2 + j] - mn);
                    sc[nt][hf * 2 + j] = p;
                    rs += p;
                }
            rs += __shfl_xor_sync(~0u, rs, 1);
            rs += __shfl_xor_sync(~0u, rs, 2);
            lrow[hf] = lrow[hf] * fct[hf] + rs;
        }
        if (__ballot_sync(0xffffffffu, (fct[0] != 1.f) || (fct[1] != 1.f))) {
#pragma unroll
            for (int nt = 0; nt < 16; nt++) {
                o[nt][0] *= fct[0];
                o[nt][1] *= fct[0];
                o[nt][2] *= fct[1];
                o[nt][3] *= fct[1];
            }
        }
        // P @ V : P packed from registers (C-frag == A-frag layout)
#pragma unroll
        for (int ks = 0; ks < 4; ks++) {
            uint32_t af[4];
            af[0] = packh2(sc[2 * ks][0],     sc[2 * ks][1]);
            af[1] = packh2(sc[2 * ks][2],     sc[2 * ks][3]);
            af[2] = packh2(sc[2 * ks + 1][0], sc[2 * ks + 1][1]);
            af[3] = packh2(sc[2 * ks + 1][2], sc[2 * ks + 1][3]);
#pragma unroll
            for (int nb = 0; nb < 8; nb++) {
                uint32_t bf[4];
                int row = ks * 16 + ((quad & 1) << 3) + l7;  // token row
                int c = nb * 2 + (quad >> 1);                // dim chunk
                int cp = (c & 8) | ((c ^ (row & 7)) & 7);
                ldsm4t(bf, vbb + row * 256 + (cp << 4));
                mma16(o[nb * 2], af, bf[0], bf[1]);
                mma16(o[nb * 2 + 1], af, bf[2], bf[3]);
            }
        }
        __syncthreads();
        issue(kt + 2);
    }
    // epilogue
    const int r0 = warp * 16 + g2;
#pragma unroll
    for (int hf = 0; hf < 2; hf++) {
        int r = qbase + r0 + hf * 8;
        if (r < S) {
            float inv = 1.0f / lrow[hf];
#pragma unroll
            for (int nt = 0; nt < 16; nt++) {
                O[(size_t)r * DIM + head * HD + nt * 8 + 2 * q]     = o[nt][hf * 2] * inv;
                O[(size_t)r * DIM + head * HD + nt * 8 + 2 * q + 1] = o[nt][hf * 2 + 1] * inv;
            }
        }
    }
}

// ---------------- M[n][d][j] = sum_m g_kv[n,d,m] * Wlin[j,m] ----------------
__global__ __launch_bounds__(256) void prepM_k(const float* __restrict__ g_kv,
                                               const float* __restrict__ Wlin) {
    int o = blockIdx.x * 256 + threadIdx.x;
    int n = o >> 14;
    int d = (o >> 7) & 127;
    int j = o & 127;
    const float* gp = g_kv + ((size_t)n * 128 + d) * 128;
    const float* wp = Wlin + (size_t)j * 128;
    float acc = 0.f;
#pragma unroll 8
    for (int mm = 0; mm < 128; mm++) acc += gp[mm] * wp[mm];
    g_M[o] = acc;
}

// ---------------- gated: atth = half(att + z * (rq @ M_n) + blin) ----------------
__global__ __launch_bounds__(128) void gated_k(const __half* __restrict__ RQ,
                                               const float* __restrict__ blin,
                                               const float* __restrict__ att,
                                               __half* __restrict__ atth) {
    const int s = blockIdx.x, n = blockIdx.y, j = threadIdx.x;
    __shared__ float rs[128];
    rs[j] = __half2float(RQ[(size_t)s * DIM + n * HD + j]);
    __syncthreads();
    const float* Mp = g_M + (size_t)n * (HD * HD) + j;
    float acc = 0.f;
#pragma unroll 16
    for (int d = 0; d < 128; d++) acc += rs[d] * Mp[(size_t)d * 128];
    const size_t idx = (size_t)s * DIM + n * HD + j;
    atth[idx] = __float2half(att[idx] + acc * g_z[s * NH + n] + blin[j]);
}

// ---------------- host ----------------
extern "C" void kernel_launch(void* const* d_in, const int* in_sizes, int n_in,
                              void* d_out, int out_size) {
    const float* x       = (const float*)d_in[0];
    const float* freqs   = (const float*)d_in[1];
    const float* g_kmean = (const float*)d_in[2];
    const float* g_kv    = (const float*)d_in[3];
    const float* Wq = (const float*)d_in[4];  const float* bq = (const float*)d_in[5];
    const float* Wk = (const float*)d_in[6];  const float* bk = (const float*)d_in[7];
    const float* Wv = (const float*)d_in[8];  const float* bv = (const float*)d_in[9];
    const float* Wo = (const float*)d_in[10]; const float* bo = (const float*)d_in[11];
    const float* gq = (const float*)d_in[12]; const float* gk = (const float*)d_in[13];
    const float* Wlin = (const float*)d_in[14]; const float* blin = (const float*)d_in[15];
    const int* hG = (const int*)d_in[17];
    const int* wG = (const int*)d_in[18];
    float* out = (float*)d_out;

    int S = in_sizes[0] / DIM;
    if (S > S_MAX) S = S_MAX;

    cudaFuncSetAttribute(attn_f16, cudaFuncAttributeMaxDynamicSharedMemorySize, ATT_SMEM_BYTES);
    cudaFuncSetAttribute(gemm_h, cudaFuncAttributeMaxDynamicSharedMemorySize, GEMM_SMEM_BYTES);

    float *qraw, *kraw, *att, *zbuf;
    __half *xh, *vh, *atth, *rq, *rk, *wqh, *wkh, *wvh, *woh;
    cudaGetSymbolAddress((void**)&qraw, g_qraw);
    cudaGetSymbolAddress((void**)&kraw, g_kraw);
    cudaGetSymbolAddress((void**)&att, g_att);
    cudaGetSymbolAddress((void**)&xh, g_xh);
    cudaGetSymbolAddress((void**)&vh, g_vh);
    cudaGetSymbolAddress((void**)&atth, g_atth);
    cudaGetSymbolAddress((void**)&rq, g_rq);
    cudaGetSymbolAddress((void**)&rk, g_rk);
    cudaGetSymbolAddress((void**)&wqh, g_wqh);
    cudaGetSymbolAddress((void**)&wkh, g_wkh);
    cudaGetSymbolAddress((void**)&wvh, g_wvh);
    cudaGetSymbolAddress((void**)&woh, g_woh);
    cudaGetSymbolAddress((void**)&zbuf, g_z);

    dim3 gemmGrid((S + 127) / 128, DIM / 128);
    const int n4x = S * DIM / 4, n4w = DIM * DIM / 4;
    const float kscale = 0.08838834764831845f * 1.44269504088896341f;  // 128^-.5 * log2e

    conv_h<<<(n4x + 255) / 256, 256>>>(x, xh, n4x);
    conv_h<<<(n4w + 255) / 256, 256>>>(Wq, wqh, n4w);
    conv_h<<<(n4w + 255) / 256, 256>>>(Wk, wkh, n4w);
    conv_h<<<(n4w + 255) / 256, 256>>>(Wv, wvh, n4w);
    conv_h<<<(n4w + 255) / 256, 256>>>(Wo, woh, n4w);
    rope_table_k<<<S, 64>>>(freqs, hG, wG);
    gemm_h<<<gemmGrid, 256, GEMM_SMEM_BYTES>>>(xh, wqh, bq, qraw, (__half*)nullptr, S);
    gemm_h<<<gemmGrid, 256, GEMM_SMEM_BYTES>>>(xh, wkh, bk, kraw, (__half*)nullptr, S);
    gemm_h<<<gemmGrid, 256, GEMM_SMEM_BYTES>>>(xh, wvh, bv, (float*)nullptr, vh, S);
    rmsrope_k<<<S, 384>>>(qraw, gq, g_kmean, rq, zbuf, 1, 1.0f);
    rmsrope_k<<<S, 384>>>(kraw, gk, g_kmean, rk, zbuf, 0, kscale);
    prepM_k<<<768, 256>>>(g_kv, Wlin);
    attn_f16<<<dim3((S + 127) / 128, NH), 256, ATT_SMEM_BYTES>>>(rq, rk, vh, att, S);
    gated_k<<<dim3(S, NH), 128>>>(rq, blin, att, atth);
    gemm_h<<<gemmGrid, 256, GEMM_SMEM_BYTES>>>(atth, woh, bo, out, (__half*)nullptr, S);
}

// round 7
// speedup vs baseline: 7.8146x; 1.3372x over previous
#include <cuda_runtime.h>
#include <cuda_fp16.h>
#include <cstdint>

#define DIM 1536
#define NH 12
#define HD 128
#define S_MAX 4680

// ---------------- scratch ----------------
__device__ float  g_qraw[S_MAX * DIM];
__device__ float  g_kraw[S_MAX * DIM];
__device__ float  g_att[S_MAX * DIM];
__device__ __half g_xh[S_MAX * DIM];
__device__ __half g_vh[S_MAX * DIM];
__device__ __half g_atth[S_MAX * DIM];
__device__ __half g_rq[S_MAX * DIM];
__device__ __half g_rk[S_MAX * DIM];
__device__ __half g_wqh[DIM * DIM];
__device__ __half g_wkh[DIM * DIM];
__device__ __half g_wvh[DIM * DIM];
__device__ __half g_woh[DIM * DIM];
__device__ float  g_rope[S_MAX * HD];
__device__ float  g_z[S_MAX * NH];
__device__ __half g_Mh[NH * HD * HD];   // [n][j][d] fp16 (transposed for NT mma)

// ---------------- helpers ----------------
__device__ __forceinline__ uint32_t smaddr(const void* p) {
    return (uint32_t)__cvta_generic_to_shared(p);
}
__device__ __forceinline__ void ldsm4(uint32_t* r, uint32_t a) {
    asm volatile("ldmatrix.sync.aligned.m8n8.x4.shared.b16 {%0,%1,%2,%3},[%4];"
                 : "=r"(r[0]), "=r"(r[1]), "=r"(r[2]), "=r"(r[3]) : "r"(a));
}
__device__ __forceinline__ void ldsm4t(uint32_t* r, uint32_t a) {
    asm volatile("ldmatrix.sync.aligned.m8n8.x4.trans.shared.b16 {%0,%1,%2,%3},[%4];"
                 : "=r"(r[0]), "=r"(r[1]), "=r"(r[2]), "=r"(r[3]) : "r"(a));
}
__device__ __forceinline__ void mma16(float* c, const uint32_t* a, uint32_t b0, uint32_t b1) {
    asm volatile(
        "mma.sync.aligned.m16n8k16.row.col.f32.f16.f16.f32 "
        "{%0,%1,%2,%3},{%4,%5,%6,%7},{%8,%9},{%0,%1,%2,%3};\n"
        : "+f"(c[0]), "+f"(c[1]), "+f"(c[2]), "+f"(c[3])
        : "r"(a[0]), "r"(a[1]), "r"(a[2]), "r"(a[3]), "r"(b0), "r"(b1));
}
__device__ __forceinline__ uint32_t packh2(float x, float y) {
    __half2 h = __floats2half2_rn(x, y);
    return *reinterpret_cast<uint32_t*>(&h);
}
__device__ __forceinline__ void cpa16(uint32_t dst, const void* src, int sb) {
    asm volatile("cp.async.cg.shared.global [%0], [%1], 16, %2;" :: "r"(dst), "l"(src), "r"(sb));
}
#define CP_COMMIT() asm volatile("cp.async.commit_group;" ::: "memory")
#define CP_WAIT1()  asm volatile("cp.async.wait_group 1;" ::: "memory")
#define CP_WAIT2()  asm volatile("cp.async.wait_group 2;" ::: "memory")

// ---------------- fp32 -> fp16 convert ----------------
__global__ void conv_h(const float* __restrict__ src, __half* __restrict__ dst, int n4) {
    int i = blockIdx.x * 256 + threadIdx.x;
    if (i < n4) {
        float4 v = ((const float4*)src)[i];
        ((__half2*)dst)[2 * i]     = __floats2half2_rn(v.x, v.y);
        ((__half2*)dst)[2 * i + 1] = __floats2half2_rn(v.z, v.w);
    }
}

// ---------------- rope table ----------------
__global__ void rope_table_k(const float* __restrict__ freqs,
                             const int* __restrict__ hg, const int* __restrict__ wg) {
    int s = blockIdx.x;
    int i = threadIdx.x;
    int h = hg[0], w = wg[0];
    int hw = h * w;
    int fi = s / hw;
    int rem = s - fi * hw;
    int hi = rem / w;
    int wi = rem - hi * w;
    int r = (i < 22) ? fi : ((i < 43) ? hi : wi);
    float2 v = ((const float2*)freqs)[r * 64 + i];
    ((float2*)g_rope)[s * 64 + i] = v;
}

// ---------------- fp16 NT GEMM, cp.async 3-stage: C = A * B^T + bias ----------------
#define GEMM_SMEM_BYTES (6 * 128 * 64 * 2)  // 3 stages x (A+B) x 16KB = 96KB

__global__ __launch_bounds__(256, 2) void gemm_h(const __half* __restrict__ A,
                                                 const __half* __restrict__ B,
                                                 const float* __restrict__ bias,
                                                 float* __restrict__ C,
                                                 __half* __restrict__ Ch, int M) {
    extern __shared__ __align__(16) __half gsm[];
    __half* As = gsm;                    // [3][128*64]
    __half* Bs = gsm + 3 * 128 * 64;     // [3][128*64]
    const uint32_t asb = smaddr(As), bsb = smaddr(Bs);
    const int tid = threadIdx.x, lane = tid & 31, warp = tid >> 5;
    const int wm = warp >> 2, wn = warp & 3, q = lane & 3, g2 = lane >> 2;
    const int quad = lane >> 3, l7 = lane & 7;
    const int mbase = blockIdx.x * 128, nbase = blockIdx.y * 128;
    const int NK = DIM / 64;  // 24

    float acc[4][4][4];
#pragma unroll
    for (int i = 0; i < 4; i++)
#pragma unroll
        for (int j = 0; j < 4; j++)
#pragma unroll
            for (int k = 0; k < 4; k++) acc[i][j][k] = 0.f;

    auto issue = [&](int s) {
        if (s < NK) {
            int k0 = s * 64;
            int st = s % 3;
            uint32_t ad = asb + st * 16384;
            uint32_t bd = bsb + st * 16384;
#pragma unroll
            for (int it = 0; it < 4; it++) {
                int idx = tid + it * 256;
                int r = idx >> 3, c = idx & 7;
                int off = r * 128 + ((c ^ (r & 7)) << 4);
                int arow = mbase + r;
                int ar = arow < M ? arow : M - 1;
                cpa16(ad + off, A + (size_t)ar * DIM + k0 + c * 8, arow < M ? 16 : 0);
                cpa16(bd + off, B + (size_t)(nbase + r) * DIM + k0 + c * 8, 16);
            }
        }
        CP_COMMIT();
    };

    issue(0);
    issue(1);
    issue(2);

    for (int kt = 0; kt < NK; kt++) {
        CP_WAIT2();
        __syncthreads();
        int st = kt % 3;
        uint32_t ab = asb + st * 16384;
        uint32_t bb = bsb + st * 16384;
#pragma unroll
        for (int ks = 0; ks < 4; ks++) {
            uint32_t af[4][4];
#pragma unroll
            for (int mt = 0; mt < 4; mt++) {
                int row = wm * 64 + mt * 16 + ((quad & 1) << 3) + l7;
                int c = ks * 2 + (quad >> 1);
                ldsm4(af[mt], ab + row * 128 + ((c ^ (row & 7)) << 4));
            }
#pragma unroll
            for (int nb = 0; nb < 2; nb++) {
                uint32_t bf[4];
                int n = wn * 32 + nb * 16 + ((quad >> 1) << 3) + l7;
                int c = ks * 2 + (quad & 1);
                ldsm4(bf, bb + n * 128 + ((c ^ (n & 7)) << 4));
#pragma unroll
                for (int mt = 0; mt < 4; mt++) {
                    mma16(acc[mt][nb * 2], af[mt], bf[0], bf[1]);
                    mma16(acc[mt][nb * 2 + 1], af[mt], bf[2], bf[3]);
                }
            }
        }
        __syncthreads();
        issue(kt + 3);
    }
#pragma unroll
    for (int mt = 0; mt < 4; mt++) {
        int r0 = mbase + wm * 64 + mt * 16 + g2;
#pragma unroll
        for (int nt = 0; nt < 4; nt++) {
            int c0 = nbase + wn * 32 + nt * 8 + 2 * q;
            float v0 = acc[mt][nt][0] + bias[c0];
            float v1 = acc[mt][nt][1] + bias[c0 + 1];
            float v2 = acc[mt][nt][2] + bias[c0];
            float v3 = acc[mt][nt][3] + bias[c0 + 1];
            if (Ch) {
                if (r0 < M)
                    *(__half2*)(Ch + (size_t)r0 * DIM + c0) = __floats2half2_rn(v0, v1);
                if (r0 + 8 < M)
                    *(__half2*)(Ch + (size_t)(r0 + 8) * DIM + c0) = __floats2half2_rn(v2, v3);
            } else {
                if (r0 < M) {
                    C[(size_t)r0 * DIM + c0] = v0;
                    C[(size_t)r0 * DIM + c0 + 1] = v1;
                }
                if (r0 + 8 < M) {
                    C[(size_t)(r0 + 8) * DIM + c0] = v2;
                    C[(size_t)(r0 + 8) * DIM + c0 + 1] = v3;
                }
            }
        }
    }
}

// ---------------- RMS + RoPE + optional z ; fp16 output with prescale ----------------
__global__ __launch_bounds__(384) void rmsrope_k(const float* __restrict__ in,
                                                 const float* __restrict__ g,
                                                 const float* __restrict__ gkm,
                                                 __half* __restrict__ out,
                                                 float* __restrict__ zout, int doZ,
                                                 float prescale) {
    const int s = blockIdx.x;
    const int t = threadIdx.x;
    const int warp = t >> 5, lane = t & 31;
    float4 v = ((const float4*)(in + (size_t)s * DIM))[t];
    float ss = v.x * v.x + v.y * v.y + v.z * v.z + v.w * v.w;
#pragma unroll
    for (int off = 16; off; off >>= 1) ss += __shfl_xor_sync(~0u, ss, off);
    __shared__ float red[12];
    __shared__ float sinv;
    if (lane == 0) red[warp] = ss;
    __syncthreads();
    if (t == 0) {
        float tot = 0;
#pragma unroll
        for (int i = 0; i < 12; i++) tot += red[i];
        sinv = rsqrtf(tot * (1.0f / DIM) + 1e-6f);
    }
    __syncthreads();
    const float inv = sinv;
    const int e = t * 4;
    float y0 = v.x * inv * g[e + 0];
    float y1 = v.y * inv * g[e + 1];
    float y2 = v.z * inv * g[e + 2];
    float y3 = v.w * inv * g[e + 3];
    if (doZ) {
        float zp = fmaxf(y0, 0.f) * gkm[e + 0] + fmaxf(y1, 0.f) * gkm[e + 1] +
                   fmaxf(y2, 0.f) * gkm[e + 2] + fmaxf(y3, 0.f) * gkm[e + 3];
#pragma unroll
        for (int off = 16; off; off >>= 1) zp += __shfl_xor_sync(~0u, zp, off);
        if (lane == 0) zout[s * NH + warp] = 1.0f / (zp + 1e-6f);
    }
    const int i0 = (2 * t) & 63;
    const float* rp = g_rope + (size_t)s * HD + i0 * 2;
    float c0 = rp[0], s0 = rp[1], c1 = rp[2], s1 = rp[3];
    float o0 = (y0 * c0 - y1 * s0) * prescale;
    float o1 = (y0 * s0 + y1 * c0) * prescale;
    float o2 = (y2 * c1 - y3 * s1) * prescale;
    float o3 = (y2 * s1 + y3 * c1) * prescale;
    __half2* op = (__half2*)(out + (size_t)s * DIM);
    op[t * 2]     = __floats2half2_rn(o0, o1);
    op[t * 2 + 1] = __floats2half2_rn(o2, o3);
}

// ---------------- fp16 flash attention: 2 CTAs/SM, cp.async 2-stage, register P ----------------
#define KS_BYTES 16384
#define ATT_SMEM_BYTES ((128 * 128 + 4 * 64 * 128) * 2)  // 96KB

__global__ __launch_bounds__(256, 2) void attn_f16(const __half* __restrict__ RQ,
                                                   const __half* __restrict__ RK,
                                                   const __half* __restrict__ V,
                                                   float* __restrict__ O, int S) {
    extern __shared__ __align__(16) __half smh[];
    __half* Qs = smh;                         // 128 x 128
    __half* Ks = smh + 128 * 128;             // [2] x 64 x 128
    __half* Vs = smh + 128 * 128 + 2 * 64 * 128;
    const uint32_t qsb = smaddr(Qs), ksb = smaddr(Ks), vsb = smaddr(Vs);
    const int tid = threadIdx.x, lane = tid & 31, warp = tid >> 5;
    const int q = lane & 3, g2 = lane >> 2, quad = lane >> 3, l7 = lane & 7;
    const int head = blockIdx.y;
    const int qbase = blockIdx.x * 128;
    const int nkt = (S + 63) >> 6;

    // Q tile
#pragma unroll
    for (int it = 0; it < 8; it++) {
        int idx = tid + it * 256;
        int r = idx >> 4, c = idx & 15;
        uint4 v = make_uint4(0, 0, 0, 0);
        if (qbase + r < S) v = *(const uint4*)(RQ + (size_t)(qbase + r) * DIM + head * HD + c * 8);
        int cp = (c & 8) | ((c ^ (r & 7)) & 7);
        *(uint4*)((char*)Qs + r * 256 + (cp << 4)) = v;
    }

    auto issue = [&](int s) {
        if (s < nkt) {
            int kb = s * 64;
            uint32_t kd = ksb + (s & 1) * KS_BYTES;
            uint32_t vd = vsb + (s & 1) * KS_BYTES;
#pragma unroll
            for (int it = 0; it < 4; it++) {
                int idx = tid + it * 256;
                int r = idx >> 4, c = idx & 15;
                int row = kb + r;
                int rc = row < S ? row : S - 1;
                int sb = row < S ? 16 : 0;
                int cp = (c & 8) | ((c ^ (r & 7)) & 7);
                int off = r * 256 + (cp << 4);
                const size_t go = (size_t)rc * DIM + head * HD + c * 8;
                cpa16(kd + off, RK + go, sb);
                cpa16(vd + off, V + go, sb);
            }
        }
        CP_COMMIT();
    };
    issue(0);
    issue(1);
    __syncthreads();

    float o[16][4];
    float mrow[2], lrow[2];
#pragma unroll
    for (int i = 0; i < 16; i++)
#pragma unroll
        for (int j = 0; j < 4; j++) o[i][j] = 0.f;
    mrow[0] = mrow[1] = -1e30f;
    lrow[0] = lrow[1] = 0.f;

    for (int kt = 0; kt < nkt; kt++) {
        const int kb = kt * 64;
        CP_WAIT1();
        __syncthreads();
        const uint32_t kbb = ksb + (kt & 1) * KS_BYTES;
        const uint32_t vbb = vsb + (kt & 1) * KS_BYTES;

        // QK^T (log2-domain; K pre-scaled by 128^-.5*log2e); Q frags reloaded per ks
        float sc[8][4];
#pragma unroll
        for (int nt = 0; nt < 8; nt++)
#pragma unroll
            for (int j = 0; j < 4; j++) sc[nt][j] = 0.f;
#pragma unroll
        for (int ks = 0; ks < 8; ks++) {
            uint32_t af[4];
            {
                int row = warp * 16 + ((quad & 1) << 3) + l7;
                int c = ks * 2 + (quad >> 1);
                int cp = (c & 8) | ((c ^ (row & 7)) & 7);
                ldsm4(af, qsb + row * 256 + (cp << 4));
            }
#pragma unroll
            for (int nb = 0; nb < 4; nb++) {
                uint32_t bf[4];
                int n = nb * 16 + ((quad >> 1) << 3) + l7;
                int c = ks * 2 + (quad & 1);
                int cp = (c & 8) | ((c ^ (n & 7)) & 7);
                ldsm4(bf, kbb + n * 256 + (cp << 4));
                mma16(sc[nb * 2], af, bf[0], bf[1]);
                mma16(sc[nb * 2 + 1], af, bf[2], bf[3]);
            }
        }
        // online softmax (exp2); sc becomes P
        float fct[2];
#pragma unroll
        for (int hf = 0; hf < 2; hf++) {
            float tm = -1e30f;
#pragma unroll
            for (int nt = 0; nt < 8; nt++)
#pragma unroll
                for (int j = 0; j < 2; j++) {
                    int col = kb + nt * 8 + 2 * q + j;
                    float v = (col < S) ? sc[nt][hf * 2 + j] : -1e30f;
                    sc[nt][hf * 2 + j] = v;
                    tm = fmaxf(tm, v);
                }
            tm = fmaxf(tm, __shfl_xor_sync(~0u, tm, 1));
            tm = fmaxf(tm, __shfl_xor_sync(~0u, tm, 2));
            float mn = fmaxf(mrow[hf], tm);
            fct[hf] = exp2f(mrow[hf] - mn);
            mrow[hf] = mn;
            float rs = 0.f;
#pragma unroll
            for (int nt = 0; nt < 8; nt++)
#pragma unroll
                for (int j = 0; j < 2; j++) {
                    float p = exp2f(sc[nt][hf * 2 + j] - mn);
                    sc[nt][hf * 2 + j] = p;
                    rs += p;
                }
            rs += __shfl_xor_sync(~0u, rs, 1);
            rs += __shfl_xor_sync(~0u, rs, 2);
            lrow[hf] = lrow[hf] * fct[hf] + rs;
        }
        if (__ballot_sync(0xffffffffu, (fct[0] != 1.f) || (fct[1] != 1.f))) {
#pragma unroll
            for (int nt = 0; nt < 16; nt++) {
                o[nt][0] *= fct[0];
                o[nt][1] *= fct[0];
                o[nt][2] *= fct[1];
                o[nt][3] *= fct[1];
            }
        }
        // P @ V : P packed from registers (C-frag == A-frag layout)
#pragma unroll
        for (int ks = 0; ks < 4; ks++) {
            uint32_t af[4];
            af[0] = packh2(sc[2 * ks][0],     sc[2 * ks][1]);
            af[1] = packh2(sc[2 * ks][2],     sc[2 * ks][3]);
            af[2] = packh2(sc[2 * ks + 1][0], sc[2 * ks + 1][1]);
            af[3] = packh2(sc[2 * ks + 1][2], sc[2 * ks + 1][3]);
#pragma unroll
            for (int nb = 0; nb < 8; nb++) {
                uint32_t bf[4];
                int row = ks * 16 + ((quad & 1) << 3) + l7;  // token row
                int c = nb * 2 + (quad >> 1);                // dim chunk
                int cp = (c & 8) | ((c ^ (row & 7)) & 7);
                ldsm4t(bf, vbb + row * 256 + (cp << 4));
                mma16(o[nb * 2], af, bf[0], bf[1]);
                mma16(o[nb * 2 + 1], af, bf[2], bf[3]);
            }
        }
        __syncthreads();
        issue(kt + 2);
    }
    // epilogue
    const int r0 = warp * 16 + g2;
#pragma unroll
    for (int hf = 0; hf < 2; hf++) {
        int r = qbase + r0 + hf * 8;
        if (r < S) {
            float inv = 1.0f / lrow[hf];
#pragma unroll
            for (int nt = 0; nt < 16; nt++) {
                O[(size_t)r * DIM + head * HD + nt * 8 + 2 * q]     = o[nt][hf * 2] * inv;
                O[(size_t)r * DIM + head * HD + nt * 8 + 2 * q + 1] = o[nt][hf * 2 + 1] * inv;
            }
        }
    }
}

// ---------------- Mh[n][j][d] = half( sum_m g_kv[n,d,m] * Wlin[j,m] ) ----------------
__global__ __launch_bounds__(256) void prepM_k(const float* __restrict__ g_kv,
                                               const float* __restrict__ Wlin) {
    int o = blockIdx.x * 256 + threadIdx.x;   // n*16384 + j*128 + d
    int n = o >> 14;
    int j = (o >> 7) & 127;
    int d = o & 127;
    const float* gp = g_kv + ((size_t)n * 128 + d) * 128;
    const float* wp = Wlin + (size_t)j * 128;
    float acc = 0.f;
#pragma unroll 8
    for (int mm = 0; mm < 128; mm++) acc += gp[mm] * wp[mm];
    g_Mh[o] = __float2half(acc);
}

// ---------------- gated MMA: atth = half(att + z*(rq @ Mh_n^T) + blin) ----------------
#define GATED_SMEM_BYTES (2 * 128 * 128 * 2)  // A + B, 64KB

__global__ __launch_bounds__(256, 2) void gatedmma_k(const __half* __restrict__ RQ,
                                                     const __half* __restrict__ Mh,
                                                     const float* __restrict__ blin,
                                                     const float* __restrict__ att,
                                                     const float* __restrict__ zbuf,
                                                     __half* __restrict__ atth, int S) {
    extern __shared__ __align__(16) __half gsm2[];
    __half* As = gsm2;                 // 128 x 128 (256B rows, swizzled)
    __half* Bs = gsm2 + 128 * 128;
    const uint32_t asb = smaddr(As), bsb = smaddr(Bs);
    const int tid = threadIdx.x, lane = tid & 31, warp = tid >> 5;
    const int wm = warp >> 2, wn = warp & 3, q = lane & 3, g2 = lane >> 2;
    const int quad = lane >> 3, l7 = lane & 7;
    const int head = blockIdx.y;
    const int qbase = blockIdx.x * 128;

    // A: rq rows; B: Mh rows (j), both 128x128
#pragma unroll
    for (int it = 0; it < 8; it++) {
        int idx = tid + it * 256;
        int r = idx >> 4, c = idx & 15;
        int cp = (c & 8) | ((c ^ (r & 7)) & 7);
        uint4 va = make_uint4(0, 0, 0, 0);
        if (qbase + r < S) va = *(const uint4*)(RQ + (size_t)(qbase + r) * DIM + head * HD + c * 8);
        *(uint4*)((char*)As + r * 256 + (cp << 4)) = va;
        uint4 vb = *(const uint4*)(Mh + (size_t)head * HD * HD + r * HD + c * 8);
        *(uint4*)((char*)Bs + r * 256 + (cp << 4)) = vb;
    }
    __syncthreads();

    float acc[4][4][4];
#pragma unroll
    for (int i = 0; i < 4; i++)
#pragma unroll
        for (int j = 0; j < 4; j++)
#pragma unroll
            for (int k = 0; k < 4; k++) acc[i][j][k] = 0.f;

#pragma unroll
    for (int ks = 0; ks < 8; ks++) {
        uint32_t af[4][4];
#pragma unroll
        for (int mt = 0; mt < 4; mt++) {
            int row = wm * 64 + mt * 16 + ((quad & 1) << 3) + l7;
            int c = ks * 2 + (quad >> 1);
            int cp = (c & 8) | ((c ^ (row & 7)) & 7);
            ldsm4(af[mt], asb + row * 256 + (cp << 4));
        }
#pragma unroll
        for (int nb = 0; nb < 2; nb++) {
            uint32_t bf[4];
            int n = wn * 32 + nb * 16 + ((quad >> 1) << 3) + l7;
            int c = ks * 2 + (quad & 1);
            int cp = (c & 8) | ((c ^ (n & 7)) & 7);
            ldsm4(bf, bsb + n * 256 + (cp << 4));
#pragma unroll
            for (int mt = 0; mt < 4; mt++) {
                mma16(acc[mt][nb * 2], af[mt], bf[0], bf[1]);
                mma16(acc[mt][nb * 2 + 1], af[mt], bf[2], bf[3]);
            }
        }
    }
#pragma unroll
    for (int mt = 0; mt < 4; mt++) {
        int r0 = qbase + wm * 64 + mt * 16 + g2;
        float z0 = (r0 < S) ? zbuf[r0 * NH + head] : 0.f;
        float z1 = (r0 + 8 < S) ? zbuf[(r0 + 8) * NH + head] : 0.f;
#pragma unroll
        for (int nt = 0; nt < 4; nt++) {
            int c0 = wn * 32 + nt * 8 + 2 * q;
            float b0 = blin[c0], b1 = blin[c0 + 1];
            if (r0 < S) {
                size_t i0 = (size_t)r0 * DIM + head * HD + c0;
                *(__half2*)(atth + i0) = __floats2half2_rn(
                    att[i0] + acc[mt][nt][0] * z0 + b0,
                    att[i0 + 1] + acc[mt][nt][1] * z0 + b1);
            }
            if (r0 + 8 < S) {
                size_t i1 = (size_t)(r0 + 8) * DIM + head * HD + c0;
                *(__half2*)(atth + i1) = __floats2half2_rn(
                    att[i1] + acc[mt][nt][2] * z1 + b0,
                    att[i1 + 1] + acc[mt][nt][3] * z1 + b1);
            }
        }
    }
}

// ---------------- host ----------------
extern "C" void kernel_launch(void* const* d_in, const int* in_sizes, int n_in,
                              void* d_out, int out_size) {
    const float* x       = (const float*)d_in[0];
    const float* freqs   = (const float*)d_in[1];
    const float* g_kmean = (const float*)d_in[2];
    const float* g_kv    = (const float*)d_in[3];
    const float* Wq = (const float*)d_in[4];  const float* bq = (const float*)d_in[5];
    const float* Wk = (const float*)d_in[6];  const float* bk = (const float*)d_in[7];
    const float* Wv = (const float*)d_in[8];  const float* bv = (const float*)d_in[9];
    const float* Wo = (const float*)d_in[10]; const float* bo = (const float*)d_in[11];
    const float* gq = (const float*)d_in[12]; const float* gk = (const float*)d_in[13];
    const float* Wlin = (const float*)d_in[14]; const float* blin = (const float*)d_in[15];
    const int* hG = (const int*)d_in[17];
    const int* wG = (const int*)d_in[18];
    float* out = (float*)d_out;

    int S = in_sizes[0] / DIM;
    if (S > S_MAX) S = S_MAX;

    cudaFuncSetAttribute(attn_f16, cudaFuncAttributeMaxDynamicSharedMemorySize, ATT_SMEM_BYTES);
    cudaFuncSetAttribute(gemm_h, cudaFuncAttributeMaxDynamicSharedMemorySize, GEMM_SMEM_BYTES);
    cudaFuncSetAttribute(gatedmma_k, cudaFuncAttributeMaxDynamicSharedMemorySize, GATED_SMEM_BYTES);

    float *qraw, *kraw, *att, *zbuf;
    __half *xh, *vh, *atth, *rq, *rk, *wqh, *wkh, *wvh, *woh, *mh;
    cudaGetSymbolAddress((void**)&qraw, g_qraw);
    cudaGetSymbolAddress((void**)&kraw, g_kraw);
    cudaGetSymbolAddress((void**)&att, g_att);
    cudaGetSymbolAddress((void**)&xh, g_xh);
    cudaGetSymbolAddress((void**)&vh, g_vh);
    cudaGetSymbolAddress((void**)&atth, g_atth);
    cudaGetSymbolAddress((void**)&rq, g_rq);
    cudaGetSymbolAddress((void**)&rk, g_rk);
    cudaGetSymbolAddress((void**)&wqh, g_wqh);
    cudaGetSymbolAddress((void**)&wkh, g_wkh);
    cudaGetSymbolAddress((void**)&wvh, g_wvh);
    cudaGetSymbolAddress((void**)&woh, g_woh);
    cudaGetSymbolAddress((void**)&mh, g_Mh);
    cudaGetSymbolAddress((void**)&zbuf, g_z);

    dim3 gemmGrid((S + 127) / 128, DIM / 128);
    dim3 gatedGrid((S + 127) / 128, NH);
    const int n4x = S * DIM / 4, n4w = DIM * DIM / 4;
    const float kscale = 0.08838834764831845f * 1.44269504088896341f;  // 128^-.5 * log2e

    conv_h<<<(n4x + 255) / 256, 256>>>(x, xh, n4x);
    conv_h<<<(n4w + 255) / 256, 256>>>(Wq, wqh, n4w);
    conv_h<<<(n4w + 255) / 256, 256>>>(Wk, wkh, n4w);
    conv_h<<<(n4w + 255) / 256, 256>>>(Wv, wvh, n4w);
    conv_h<<<(n4w + 255) / 256, 256>>>(Wo, woh, n4w);
    rope_table_k<<<S, 64>>>(freqs, hG, wG);
    gemm_h<<<gemmGrid, 256, GEMM_SMEM_BYTES>>>(xh, wqh, bq, qraw, (__half*)nullptr, S);
    gemm_h<<<gemmGrid, 256, GEMM_SMEM_BYTES>>>(xh, wkh, bk, kraw, (__half*)nullptr, S);
    gemm_h<<<gemmGrid, 256, GEMM_SMEM_BYTES>>>(xh, wvh, bv, (float*)nullptr, vh, S);
    rmsrope_k<<<S, 384>>>(qraw, gq, g_kmean, rq, zbuf, 1, 1.0f);
    rmsrope_k<<<S, 384>>>(kraw, gk, g_kmean, rk, zbuf, 0, kscale);
    prepM_k<<<768, 256>>>(g_kv, Wlin);
    attn_f16<<<dim3((S + 127) / 128, NH), 256, ATT_SMEM_BYTES>>>(rq, rk, vh, att, S);
    gatedmma_k<<<gatedGrid, 256, GATED_SMEM_BYTES>>>(rq, mh, blin, att, zbuf, atth, S);
    gemm_h<<<gemmGrid, 256, GEMM_SMEM_BYTES>>>(atth, woh, bo, out, (__half*)nullptr, S);
}